// round 13
// baseline (speedup 1.0000x reference)
#include <cuda_runtime.h>
#include <cuda_fp16.h>
#include <math.h>
#include <stdint.h>

#define KC 19
#define MP 10
#define CH 720
#define CHP 768
#define JN 190
#define JP 192
#define NMAX 65536
#define TAU 6e-4f

// ---------------- scratch ----------------
__device__ __align__(256) __half g_Bh[JP * CHP];
__device__ __align__(256) float g_Bf[(size_t)JN * CH];
__device__ float g_mu[NMAX];
__device__ float g_P[NMAX];
__device__ float g_Q[NMAX];
__device__ float g_e[(size_t)NMAX * MP];
__device__ float g_c[NMAX];
__device__ float g_S[KC];
__device__ int   g_cnt[KC];
__device__ float g_T3[3][JN];   // [0]=T1 (c0-weighted), [1]=T2, [2]=T3
__device__ int      g_fixcnt;
__device__ int      g_fixn[NMAX];
__device__ unsigned g_fixmask[NMAX];

// ---------------- helpers ----------------
__device__ __forceinline__ uint32_t smem_u32(const void* p) {
    uint32_t a;
    asm("{ .reg .u64 t; cvta.to.shared.u64 t, %1; cvt.u32.u64 %0, t; }" : "=r"(a) : "l"(p));
    return a;
}
__device__ __forceinline__ float warpReduceSum(float v) {
    #pragma unroll
    for (int o = 16; o > 0; o >>= 1) v += __shfl_xor_sync(0xffffffffu, v, o);
    return v;
}
__device__ __forceinline__ float blockReduceSum(float v, float* sh) {
    __syncthreads();
    v = warpReduceSum(v);
    int lane = threadIdx.x & 31, w = threadIdx.x >> 5;
    if (lane == 0) sh[w] = v;
    __syncthreads();
    int nw = (blockDim.x + 31) >> 5;
    v = (threadIdx.x < nw) ? sh[threadIdx.x] : 0.f;
    if (w == 0) { v = warpReduceSum(v); if (lane == 0) sh[0] = v; }
    __syncthreads();
    return sh[0];
}
__device__ __forceinline__ void split2h(float a0, float a1, unsigned& h, unsigned& l) {
    __half2 hh = __floats2half2_rn(a0, a1);
    float2 hf = __half22float2(hh);
    __half2 ll = __floats2half2_rn(a0 - hf.x, a1 - hf.y);
    h = *(unsigned*)&hh;
    l = *(unsigned*)&ll;
}

#define LDMX4(r0, r1, r2, r3, addr) \
    asm volatile("ldmatrix.sync.aligned.m8n8.x4.shared.b16 {%0,%1,%2,%3}, [%4];" \
                 : "=r"(r0), "=r"(r1), "=r"(r2), "=r"(r3) : "r"(addr))

#define MMA16816H(d, a, b0, b1) \
    asm volatile("mma.sync.aligned.m16n8k16.row.col.f32.f16.f16.f32 " \
                 "{%0,%1,%2,%3}, {%4,%5,%6,%7}, {%8,%9}, {%0,%1,%2,%3};" \
                 : "+f"((d)[0]), "+f"((d)[1]), "+f"((d)[2]), "+f"((d)[3]) \
                 : "r"((a)[0]), "r"((a)[1]), "r"((a)[2]), "r"((a)[3]), "r"(b0), "r"(b1))

#define CP_ASYNC16(dst, src) \
    asm volatile("cp.async.ca.shared.global [%0], [%1], 16;" \
                 :: "r"(dst), "l"(src) : "memory")

// ---------------- K0: warp-per-row stats ----------------
__global__ __launch_bounds__(256) void kstats(const float* __restrict__ x,
                                              const float* __restrict__ gamma,
                                              const float* __restrict__ beta, int N) {
    int warp = threadIdx.x >> 5, lane = threadIdx.x & 31;
    int n = blockIdx.x * 8 + warp;
    if (n >= N) return;
    const float4* xr = (const float4*)(x + (size_t)n * CH);
    float4 v[6];
    float s = 0.f, sq = 0.f;
    #pragma unroll
    for (int i = 0; i < 6; i++) {
        int idx = i * 32 + lane;
        if (idx < 180) {
            v[i] = xr[idx];
            s += v[i].x + v[i].y + v[i].z + v[i].w;
            sq += v[i].x * v[i].x + v[i].y * v[i].y + v[i].z * v[i].z + v[i].w * v[i].w;
        } else v[i] = make_float4(0, 0, 0, 0);
    }
    s = warpReduceSum(s);
    sq = warpReduceSum(sq);
    float mu = s * (1.f / (float)CH);
    float rs = rsqrtf(sq * (1.f / (float)CH) - mu * mu + 1e-5f);
    float yn = 0.f;
    #pragma unroll
    for (int i = 0; i < 6; i++) {
        int idx = i * 32 + lane;
        if (idx < 180) {
            float4 g4 = ((const float4*)gamma)[idx];
            float4 b4 = ((const float4*)beta)[idx];
            float a = (v[i].x - mu) * rs * g4.x + b4.x;
            float b = (v[i].y - mu) * rs * g4.y + b4.y;
            float c = (v[i].z - mu) * rs * g4.z + b4.z;
            float d = (v[i].w - mu) * rs * g4.w + b4.w;
            yn += a * a + b * b + c * c + d * d;
        }
    }
    yn = warpReduceSum(yn);
    float inv = 1.f / fmaxf(sqrtf(yn), 1e-12f);
    if (lane == 0) { g_mu[n] = mu; g_P[n] = rs * inv; g_Q[n] = inv; }
}

// ---------------- K1: normalize prototypes (fp16 + fp32) + init ----------------
__global__ __launch_bounds__(192) void kprotoB(const float* __restrict__ proto) {
    int p = blockIdx.x;
    int t = threadIdx.x;
    __shared__ float sh[32];
    if (p == JN) {
        ((uint2*)(g_Bh + (size_t)190 * CHP))[t] = make_uint2(0u, 0u);
        ((uint2*)(g_Bh + (size_t)191 * CHP))[t] = make_uint2(0u, 0u);
        if (t < KC) { g_S[t] = 0.f; g_cnt[t] = 0; }
        if (t == 0) g_fixcnt = 0;
        for (int j = t; j < 3 * JN; j += 192) ((float*)g_T3)[j] = 0.f;
        return;
    }
    int k = p / MP, m = p % MP;
    int j = m * KC + k;
    const float4* pr = (const float4*)(proto + (size_t)p * CH);
    float4 v = make_float4(0, 0, 0, 0);
    float ss = 0.f;
    if (t < 180) {
        v = pr[t];
        ss = v.x * v.x + v.y * v.y + v.z * v.z + v.w * v.w;
    }
    ss = blockReduceSum(ss, sh);
    float inv = 1.f / fmaxf(sqrtf(ss), 1e-12f);
    uint2 h = make_uint2(0u, 0u);
    if (t < 180) {
        float4 f = make_float4(v.x * inv, v.y * inv, v.z * inv, v.w * inv);
        __half2 h0 = __floats2half2_rn(f.x, f.y);
        __half2 h1 = __floats2half2_rn(f.z, f.w);
        h.x = *(unsigned*)&h0;
        h.y = *(unsigned*)&h1;
        ((float4*)(g_Bf + (size_t)j * CH))[t] = f;
    }
    ((uint2*)(g_Bh + (size_t)j * CHP))[t] = h;
}

// ---------------- knull: filler so GEMM is launch #4 for ncu ----------------
__global__ void knull() {
    if (threadIdx.x == 0) g_fixcnt = 0;   // redundant, keeps kernel non-empty
}

// ---------------- K2: HMMA fp16 GEMM 128x192; stats in SMEM (register relief) ----------------
// Stage s: Ahi 16K, Alo 16K, B 24K -> 56K each; stats table 2K at 2*STG.
#define STG 57344
#define STATS_OFF (2 * STG)
#define GEMM_SMEM (2 * STG + 2048)

__global__ __launch_bounds__(256, 1) void kgemm_mma(const float* __restrict__ x,
                                                    const float* __restrict__ gamma,
                                                    const float* __restrict__ beta,
                                                    float* __restrict__ sim, int N) {
    extern __shared__ char smem[];
    const uint32_t sb = smem_u32(smem);
    float4* sStats = (float4*)(smem + STATS_OFF);   // [128] {mu, P, Q, 0}

    int tid = threadIdx.x;
    int lane = tid & 31, warp = tid >> 5;        // 8 warps
    int wm = warp & 3, wn = warp >> 2;           // 4 M x 2 N
    int rowBase = (int)blockIdx.x * 128;

    int arow = tid >> 4, aq = tid & 15;          // A: rows arow + r*16 (r<8)
    int brow = tid >> 3, bq = tid & 7;           // B: rows brow + r*32 (r<6)

    float acc[2][12][4];
    #pragma unroll
    for (int t = 0; t < 2; t++)
        #pragma unroll
        for (int nt = 0; nt < 12; nt++)
            #pragma unroll
            for (int i = 0; i < 4; i++) acc[t][nt][i] = 0.f;

    float4 xr[8], g4, b4;

    auto convertA = [&](uint32_t st) {
        #pragma unroll
        for (int r = 0; r < 8; r++) {
            int row = arow + r * 16;
            float4 s4 = sStats[row];
            float yx = (xr[r].x - s4.x) * s4.y * g4.x + s4.z * b4.x;
            float yy = (xr[r].y - s4.x) * s4.y * g4.y + s4.z * b4.y;
            float yz = (xr[r].z - s4.x) * s4.y * g4.z + s4.z * b4.z;
            float yw = (xr[r].w - s4.x) * s4.y * g4.w + s4.z * b4.w;
            unsigned h0, l0, h1, l1;
            split2h(yx, yy, h0, l0);
            split2h(yz, yw, h1, l1);
            uint32_t off = (uint32_t)(row * 128 + ((aq * 8) ^ ((row & 7) << 4)));
            asm volatile("st.shared.v2.b32 [%0], {%1,%2};" :: "r"(st + off), "r"(h0), "r"(h1));
            asm volatile("st.shared.v2.b32 [%0], {%1,%2};" :: "r"(st + 16384 + off), "r"(l0), "r"(l1));
        }
    };

    auto mma_step = [&](int s, uint32_t sAhi, uint32_t sAlo, uint32_t sB) {
        uint32_t ahi[2][4], alo[2][4], bh[6][4];
        uint32_t kb = (uint32_t)(s * 32 + ((lane >> 4) & 1) * 16);
        #pragma unroll
        for (int t = 0; t < 2; t++) {
            int row = wm * 32 + t * 16 + (lane & 15);
            uint32_t off = (uint32_t)(row * 128) + (kb ^ ((uint32_t)(row & 7) << 4));
            LDMX4(ahi[t][0], ahi[t][1], ahi[t][2], ahi[t][3], sAhi + off);
            LDMX4(alo[t][0], alo[t][1], alo[t][2], alo[t][3], sAlo + off);
        }
        #pragma unroll
        for (int g = 0; g < 6; g++) {
            int row = wn * 96 + g * 16 + (lane & 15);
            uint32_t off = (uint32_t)(row * 128) + (kb ^ ((uint32_t)(row & 7) << 4));
            LDMX4(bh[g][0], bh[g][1], bh[g][2], bh[g][3], sB + off);
        }
        #pragma unroll
        for (int t = 0; t < 2; t++)
            #pragma unroll
            for (int g = 0; g < 6; g++)
                #pragma unroll
                for (int h = 0; h < 2; h++) {
                    int nt = g * 2 + h;
                    MMA16816H(acc[t][nt], ahi[t], bh[g][h], bh[g][h + 2]);
                    MMA16816H(acc[t][nt], alo[t], bh[g][h], bh[g][h + 2]);
                }
    };

    // ======== prologue ========
    {
        // cp B(0) -> stage0
        uint32_t sB = sb + 32768;
        #pragma unroll
        for (int r = 0; r < 6; r++) {
            int row = brow + r * 32;
            uint32_t off = (uint32_t)(row * 128 + ((bq * 16) ^ ((row & 7) << 4)));
            CP_ASYNC16(sB + off, (const char*)(g_Bh + (size_t)row * CHP) + bq * 16);
        }
        asm volatile("cp.async.commit_group;" ::: "memory");

        // stats table -> smem
        if (tid < 128) {
            int gr = rowBase + tid;
            float4 s4 = make_float4(0.f, 0.f, 0.f, 0.f);
            if (gr < N) { s4.x = g_mu[gr]; s4.y = g_P[gr]; s4.z = g_Q[gr]; }
            sStats[tid] = s4;
        }

        // load xr(0)
        g4 = ((const float4*)gamma)[aq];
        b4 = ((const float4*)beta)[aq];
        #pragma unroll
        for (int r = 0; r < 8; r++) {
            int gr = rowBase + arow + r * 16;
            xr[r] = (gr < N) ? ((const float4*)(x + (size_t)gr * CH))[aq]
                             : make_float4(0, 0, 0, 0);
        }
        __syncthreads();   // stats visible

        convertA(sb);      // A(0) -> stage0

        // cp B(1) -> stage1
        uint32_t nB = sb + STG + 32768;
        #pragma unroll
        for (int r = 0; r < 6; r++) {
            int row = brow + r * 32;
            uint32_t off = (uint32_t)(row * 128 + ((bq * 16) ^ ((row & 7) << 4)));
            CP_ASYNC16(nB + off, (const char*)(g_Bh + (size_t)row * CHP + 64) + bq * 16);
        }
        asm volatile("cp.async.commit_group;" ::: "memory");

        // load xr(1), g/b(1)
        g4 = ((const float4*)gamma)[16 + aq];
        b4 = ((const float4*)beta)[16 + aq];
        #pragma unroll
        for (int r = 0; r < 8; r++) {
            int gr = rowBase + arow + r * 16;
            xr[r] = (gr < N) ? ((const float4*)(x + (size_t)gr * CH))[16 + aq]
                             : make_float4(0, 0, 0, 0);
        }

        asm volatile("cp.async.wait_group 1;" ::: "memory");   // B(0) resident
        __syncthreads();
    }

    // ======== main loop ========
    for (int c = 0; c < 12; c++) {
        uint32_t st = sb + (uint32_t)(c & 1) * STG;
        uint32_t sAhi = st, sAlo = st + 16384, sB = st + 32768;

        mma_step(0, sAhi, sAlo, sB);

        if (c < 11) {
            convertA(sb + (uint32_t)((c + 1) & 1) * STG);   // A(c+1) in MMA shadow
            if (c < 10) {
                int c0 = (c + 2) * 64;
                bool kin = (c0 + aq * 4) < CH;
                g4 = kin ? ((const float4*)gamma)[(c0 >> 2) + aq] : make_float4(0, 0, 0, 0);
                b4 = kin ? ((const float4*)beta)[(c0 >> 2) + aq]  : make_float4(0, 0, 0, 0);
                #pragma unroll
                for (int r = 0; r < 8; r++) {
                    int gr = rowBase + arow + r * 16;
                    xr[r] = (kin && gr < N) ? ((const float4*)(x + (size_t)gr * CH))[(c0 >> 2) + aq]
                                            : make_float4(0, 0, 0, 0);
                }
            }
        }

        if (c != 11) {
            mma_step(1, sAhi, sAlo, sB);
            mma_step(2, sAhi, sAlo, sB);
            mma_step(3, sAhi, sAlo, sB);
        }

        if (c < 11) asm volatile("cp.async.wait_group 0;" ::: "memory");
        __syncthreads();

        if (c < 10) {
            int c0 = (c + 2) * 64;
            uint32_t nB = sb + (uint32_t)(c & 1) * STG + 32768;
            #pragma unroll
            for (int r = 0; r < 6; r++) {
                int row = brow + r * 32;
                uint32_t off = (uint32_t)(row * 128 + ((bq * 16) ^ ((row & 7) << 4)));
                CP_ASYNC16(nB + off, (const char*)(g_Bh + (size_t)row * CHP + c0) + bq * 16);
            }
            asm volatile("cp.async.commit_group;" ::: "memory");
        }
    }

    // ======== epilogue ========
    #pragma unroll
    for (int t = 0; t < 2; t++) {
        int r0 = rowBase + wm * 32 + t * 16 + (lane >> 2);
        #pragma unroll
        for (int nt = 0; nt < 12; nt++) {
            int cc = wn * 96 + nt * 8 + ((lane & 3) << 1);
            if (cc < JN) {
                if (r0 < N)
                    *(float2*)(sim + (size_t)r0 * JN + cc) =
                        make_float2(acc[t][nt][0], acc[t][nt][1]);
                if (r0 + 8 < N)
                    *(float2*)(sim + (size_t)(r0 + 8) * JN + cc) =
                        make_float2(acc[t][nt][2], acc[t][nt][3]);
            }
        }
    }
}

// ---------------- K3: kpix + near-tie flagging (round-11 tail numerics) ----------------
#define KPIX_SMEM (64 * JN * 4)
__global__ __launch_bounds__(128) void kpix(const float* __restrict__ sim,
                                            const int* __restrict__ gt,
                                            float* __restrict__ pred_out, int N) {
    extern __shared__ float srow[];
    __shared__ float sS[KC];
    __shared__ int sC[KC];
    if (threadIdx.x < KC) { sS[threadIdx.x] = 0.f; sC[threadIdx.x] = 0; }
    int base = blockIdx.x * 64;
    int npix = min(64, N - base);
    if (npix <= 0) return;
    int n4 = npix * JN / 2;
    const float2* src = (const float2*)(sim + (size_t)base * JN);
    float2* dst = (float2*)srow;
    for (int i = threadIdx.x; i < n4; i += 128) dst[i] = src[i];
    __syncthreads();
    if (threadIdx.x < npix) {
        int n = base + threadIdx.x;
        const float* row = srow + threadIdx.x * JN;
        int g = gt[n];
        float mk[KC];
        float best = -3.4e38f; int bk = 0;
        #pragma unroll
        for (int k = 0; k < KC; k++) {
            float m0 = row[k];
            #pragma unroll
            for (int m = 1; m < MP; m++) m0 = fmaxf(m0, row[m * KC + k]);
            mk[k] = m0;
            if (m0 > best) { best = m0; bk = k; }
        }
        pred_out[n] = (float)bk;
        unsigned mask = 0; int ccount = 0;
        float thr = best - TAU;
        #pragma unroll
        for (int k = 0; k < KC; k++)
            if (mk[k] > thr) { mask |= (1u << k); ccount++; }
        if (ccount > 1) {
            int idx = atomicAdd(&g_fixcnt, 1);
            g_fixn[idx] = n;
            g_fixmask[idx] = mask;
        }
        float se = 0.f;
        #pragma unroll
        for (int m = 0; m < MP; m++) {
            float e = expf(row[m * KC + g] * 20.0f);
            g_e[(size_t)n * MP + m] = e;
            se += e;
        }
        atomicAdd(&sS[g], se);
        atomicAdd(&sC[g], 1);
    }
    __syncthreads();
    if (threadIdx.x < KC) {
        if (sS[threadIdx.x] != 0.f) atomicAdd(&g_S[threadIdx.x], sS[threadIdx.x]);
        if (sC[threadIdx.x] != 0)   atomicAdd(&g_cnt[threadIdx.x], sC[threadIdx.x]);
    }
}

// ---------------- K4: exact fp32 argmax fixup ----------------
__global__ __launch_bounds__(256) void kfix(const float* __restrict__ x,
                                            const float* __restrict__ gamma,
                                            const float* __restrict__ beta,
                                            float* __restrict__ pred_out) {
    int lane = threadIdx.x & 31;
    int warp = (blockIdx.x * blockDim.x + threadIdx.x) >> 5;
    int nwarp = (gridDim.x * blockDim.x) >> 5;
    int cnt = g_fixcnt;
    for (int i = warp; i < cnt; i += nwarp) {
        int n = g_fixn[i];
        unsigned mask = g_fixmask[i];
        float mu = g_mu[n], P = g_P[n], Q = g_Q[n];
        const float4* xr = (const float4*)(x + (size_t)n * CH);
        float4 xn[6];
        #pragma unroll
        for (int q = 0; q < 6; q++) {
            int idx = q * 32 + lane;
            if (idx < 180) {
                float4 v = xr[idx];
                float4 g4 = ((const float4*)gamma)[idx];
                float4 b4 = ((const float4*)beta)[idx];
                xn[q].x = (v.x - mu) * P * g4.x + Q * b4.x;
                xn[q].y = (v.y - mu) * P * g4.y + Q * b4.y;
                xn[q].z = (v.z - mu) * P * g4.z + Q * b4.z;
                xn[q].w = (v.w - mu) * P * g4.w + Q * b4.w;
            } else xn[q] = make_float4(0, 0, 0, 0);
        }
        float best = -3.4e38f; int bk = 0;
        for (int k = 0; k < KC; k++) {
            if (!((mask >> k) & 1u)) continue;
            float smax = -3.4e38f;
            for (int m = 0; m < MP; m++) {
                const float4* pr = (const float4*)(g_Bf + (size_t)(m * KC + k) * CH);
                float d = 0.f;
                #pragma unroll
                for (int q = 0; q < 6; q++) {
                    int idx = q * 32 + lane;
                    if (idx < 180) {
                        float4 p = pr[idx];
                        d += xn[q].x * p.x + xn[q].y * p.y + xn[q].z * p.z + xn[q].w * p.w;
                    }
                }
                d = warpReduceSum(d);
                smax = fmaxf(smax, d);
            }
            if (smax > best) { best = smax; bk = k; }
        }
        if (lane == 0) pred_out[n] = (float)bk;
    }
}

// ---------------- tail (round-11 numerics, verbatim) ----------------
__global__ __launch_bounds__(256) void kT0(const int* __restrict__ gt, int N) {
    __shared__ float sT[JN];
    for (int j = threadIdx.x; j < JN; j += 256) sT[j] = 0.f;
    __syncthreads();
    int n = blockIdx.x * blockDim.x + threadIdx.x;
    if (n < N) {
        int g = gt[n];
        float c = 1.f / fmaxf(g_S[g], 1e-12f);
        g_c[n] = c;
        #pragma unroll
        for (int m = 0; m < MP; m++) atomicAdd(&sT[g * MP + m], c * g_e[(size_t)n * MP + m]);
    }
    __syncthreads();
    for (int j = threadIdx.x; j < JN; j += 256)
        if (sT[j] != 0.f) atomicAdd(&g_T3[0][j], sT[j]);
}

template<int IT>
__device__ __forceinline__ void r_chain(float* sr) {
    int t = threadIdx.x;
    if (t < JN) {
        float r = 1.f / (fmaxf(g_T3[0][t], 1e-12f) * (float)MP);
        #pragma unroll
        for (int it = 1; it < IT; it++)
            r = r / (fmaxf(r * g_T3[it][t], 1e-12f) * (float)MP);
        sr[t] = r;
    }
    __syncthreads();
}

template<int IT>
__global__ __launch_bounds__(256) void kCT(const int* __restrict__ gt, int N) {
    __shared__ float sr[JN];
    __shared__ float sT[JN];
    r_chain<IT>(sr);
    for (int j = threadIdx.x; j < JN; j += 256) sT[j] = 0.f;
    __syncthreads();
    int n = blockIdx.x * blockDim.x + threadIdx.x;
    if (n < N) {
        int g = gt[n];
        float cprev = g_c[n];
        float e[MP], V = 0.f;
        #pragma unroll
        for (int m = 0; m < MP; m++) { e[m] = g_e[(size_t)n * MP + m]; V += e[m] * sr[g * MP + m]; }
        float ns = fmaxf((float)g_cnt[g], 1.f);
        float c = cprev / (fmaxf(cprev * V, 1e-12f) * ns);
        g_c[n] = c;
        #pragma unroll
        for (int m = 0; m < MP; m++) atomicAdd(&sT[g * MP + m], c * e[m]);
    }
    __syncthreads();
    for (int j = threadIdx.x; j < JN; j += 256)
        if (sT[j] != 0.f) atomicAdd(&g_T3[IT][j], sT[j]);
}

// final: r3, c3, q scatter (q memset'd beforehand)
__global__ __launch_bounds__(256) void kCQ(const int* __restrict__ gt,
                                           float* __restrict__ qout, int N) {
    __shared__ float sr[JN];
    r_chain<3>(sr);
    int n = blockIdx.x * blockDim.x + threadIdx.x;
    if (n >= N) return;
    int g = gt[n];
    float cprev = g_c[n];
    float e[MP], V = 0.f;
    #pragma unroll
    for (int m = 0; m < MP; m++) { e[m] = g_e[(size_t)n * MP + m]; V += e[m] * sr[g * MP + m]; }
    float ns = fmaxf((float)g_cnt[g], 1.f);
    float c = cprev / (fmaxf(cprev * V, 1e-12f) * ns);
    float cs = c * ns;
    size_t base = ((size_t)g * N + n) * MP;
    #pragma unroll
    for (int m = 0; m < MP; m++)
        qout[base + m] = cs * e[m] * sr[g * MP + m];
}

// ---------------- launch ----------------
extern "C" void kernel_launch(void* const* d_in, const int* in_sizes, int n_in,
                              void* d_out, int out_size) {
    const float* x     = (const float*)d_in[0];
    const int*   gt    = (const int*)d_in[1];
    const float* gamma = (const float*)d_in[2];
    const float* beta  = (const float*)d_in[3];
    const float* proto = (const float*)d_in[4];
    int N = in_sizes[0] / CH;

    float* out  = (float*)d_out;
    float* sim  = out;
    float* q    = out + (size_t)N * JN;
    float* pred = out + 2 * (size_t)N * JN;

    cudaFuncSetAttribute(kgemm_mma, cudaFuncAttributeMaxDynamicSharedMemorySize, GEMM_SMEM);
    cudaFuncSetAttribute(kpix, cudaFuncAttributeMaxDynamicSharedMemorySize, KPIX_SMEM);

    kprotoB<<<JN + 1, 192>>>(proto);
    kstats<<<(N + 7) / 8, 256>>>(x, gamma, beta, N);
    knull<<<1, 32>>>();   // filler so kgemm is launch #4 (the one ncu captures)
    kgemm_mma<<<(N + 127) / 128, 256, GEMM_SMEM>>>(x, gamma, beta, sim, N);
    kpix<<<(N + 63) / 64, 128, KPIX_SMEM>>>(sim, gt, pred, N);
    kfix<<<256, 256>>>(x, gamma, beta, pred);

    kT0<<<(N + 255) / 256, 256>>>(gt, N);
    kCT<1><<<(N + 255) / 256, 256>>>(gt, N);
    kCT<2><<<(N + 255) / 256, 256>>>(gt, N);
    cudaMemsetAsync(q, 0, (size_t)N * JN * sizeof(float));
    kCQ<<<(N + 255) / 256, 256>>>(gt, q, N);
}

// round 14
// speedup vs baseline: 1.0164x; 1.0164x over previous
#include <cuda_runtime.h>
#include <cuda_fp16.h>
#include <math.h>
#include <stdint.h>

#define KC 19
#define MP 10
#define CH 720
#define CHP 768
#define JN 190
#define JP 192
#define NMAX 65536
#define TAU 6e-4f
#define SINKB 256

// ---------------- scratch ----------------
__device__ __align__(256) __half g_Bh[JP * CHP];
__device__ __align__(256) float g_Bf[(size_t)JN * CH];
__device__ float g_mu[NMAX];
__device__ float g_P[NMAX];
__device__ float g_Q[NMAX];
__device__ float g_e[(size_t)NMAX * MP];
__device__ float g_S[KC];
__device__ int   g_cnt[KC];
__device__ float g_T3[3][JN];   // [0]=T1 (c0-weighted), [1]=T2, [2]=T3
__device__ unsigned g_bar;

// ---------------- helpers ----------------
__device__ __forceinline__ uint32_t smem_u32(const void* p) {
    uint32_t a;
    asm("{ .reg .u64 t; cvta.to.shared.u64 t, %1; cvt.u32.u64 %0, t; }" : "=r"(a) : "l"(p));
    return a;
}
__device__ __forceinline__ float warpReduceSum(float v) {
    #pragma unroll
    for (int o = 16; o > 0; o >>= 1) v += __shfl_xor_sync(0xffffffffu, v, o);
    return v;
}
__device__ __forceinline__ float blockReduceSum(float v, float* sh) {
    __syncthreads();
    v = warpReduceSum(v);
    int lane = threadIdx.x & 31, w = threadIdx.x >> 5;
    if (lane == 0) sh[w] = v;
    __syncthreads();
    int nw = (blockDim.x + 31) >> 5;
    v = (threadIdx.x < nw) ? sh[threadIdx.x] : 0.f;
    if (w == 0) { v = warpReduceSum(v); if (lane == 0) sh[0] = v; }
    __syncthreads();
    return sh[0];
}
__device__ __forceinline__ void split2h(float a0, float a1, unsigned& h, unsigned& l) {
    __half2 hh = __floats2half2_rn(a0, a1);
    float2 hf = __half22float2(hh);
    __half2 ll = __floats2half2_rn(a0 - hf.x, a1 - hf.y);
    h = *(unsigned*)&hh;
    l = *(unsigned*)&ll;
}

#define LDMX4(r0, r1, r2, r3, addr) \
    asm volatile("ldmatrix.sync.aligned.m8n8.x4.shared.b16 {%0,%1,%2,%3}, [%4];" \
                 : "=r"(r0), "=r"(r1), "=r"(r2), "=r"(r3) : "r"(addr))

#define MMA16816H(d, a, b0, b1) \
    asm volatile("mma.sync.aligned.m16n8k16.row.col.f32.f16.f16.f32 " \
                 "{%0,%1,%2,%3}, {%4,%5,%6,%7}, {%8,%9}, {%0,%1,%2,%3};" \
                 : "+f"((d)[0]), "+f"((d)[1]), "+f"((d)[2]), "+f"((d)[3]) \
                 : "r"((a)[0]), "r"((a)[1]), "r"((a)[2]), "r"((a)[3]), "r"(b0), "r"(b1))

#define CP_ASYNC16(dst, src) \
    asm volatile("cp.async.ca.shared.global [%0], [%1], 16;" \
                 :: "r"(dst), "l"(src) : "memory")

// ---------------- K0: warp-per-row stats ----------------
__global__ __launch_bounds__(256) void kstats(const float* __restrict__ x,
                                              const float* __restrict__ gamma,
                                              const float* __restrict__ beta, int N) {
    int warp = threadIdx.x >> 5, lane = threadIdx.x & 31;
    int n = blockIdx.x * 8 + warp;
    if (n >= N) return;
    const float4* xr = (const float4*)(x + (size_t)n * CH);
    float4 v[6];
    float s = 0.f, sq = 0.f;
    #pragma unroll
    for (int i = 0; i < 6; i++) {
        int idx = i * 32 + lane;
        if (idx < 180) {
            v[i] = xr[idx];
            s += v[i].x + v[i].y + v[i].z + v[i].w;
            sq += v[i].x * v[i].x + v[i].y * v[i].y + v[i].z * v[i].z + v[i].w * v[i].w;
        } else v[i] = make_float4(0, 0, 0, 0);
    }
    s = warpReduceSum(s);
    sq = warpReduceSum(sq);
    float mu = s * (1.f / (float)CH);
    float rs = rsqrtf(sq * (1.f / (float)CH) - mu * mu + 1e-5f);
    float yn = 0.f;
    #pragma unroll
    for (int i = 0; i < 6; i++) {
        int idx = i * 32 + lane;
        if (idx < 180) {
            float4 g4 = ((const float4*)gamma)[idx];
            float4 b4 = ((const float4*)beta)[idx];
            float a = (v[i].x - mu) * rs * g4.x + b4.x;
            float b = (v[i].y - mu) * rs * g4.y + b4.y;
            float c = (v[i].z - mu) * rs * g4.z + b4.z;
            float d = (v[i].w - mu) * rs * g4.w + b4.w;
            yn += a * a + b * b + c * c + d * d;
        }
    }
    yn = warpReduceSum(yn);
    float inv = 1.f / fmaxf(sqrtf(yn), 1e-12f);
    if (lane == 0) { g_mu[n] = mu; g_P[n] = rs * inv; g_Q[n] = inv; }
}

// ---------------- K1: normalize prototypes (fp16 + fp32) + init ----------------
__global__ __launch_bounds__(192) void kprotoB(const float* __restrict__ proto) {
    int p = blockIdx.x;
    int t = threadIdx.x;
    __shared__ float sh[32];
    if (p == JN) {
        ((uint2*)(g_Bh + (size_t)190 * CHP))[t] = make_uint2(0u, 0u);
        ((uint2*)(g_Bh + (size_t)191 * CHP))[t] = make_uint2(0u, 0u);
        if (t < KC) { g_S[t] = 0.f; g_cnt[t] = 0; }
        if (t == 0) g_bar = 0u;
        for (int j = t; j < 3 * JN; j += 192) ((float*)g_T3)[j] = 0.f;
        return;
    }
    int k = p / MP, m = p % MP;
    int j = m * KC + k;
    const float4* pr = (const float4*)(proto + (size_t)p * CH);
    float4 v = make_float4(0, 0, 0, 0);
    float ss = 0.f;
    if (t < 180) {
        v = pr[t];
        ss = v.x * v.x + v.y * v.y + v.z * v.z + v.w * v.w;
    }
    ss = blockReduceSum(ss, sh);
    float inv = 1.f / fmaxf(sqrtf(ss), 1e-12f);
    uint2 h = make_uint2(0u, 0u);
    if (t < 180) {
        float4 f = make_float4(v.x * inv, v.y * inv, v.z * inv, v.w * inv);
        __half2 h0 = __floats2half2_rn(f.x, f.y);
        __half2 h1 = __floats2half2_rn(f.z, f.w);
        h.x = *(unsigned*)&h0;
        h.y = *(unsigned*)&h1;
        ((float4*)(g_Bf + (size_t)j * CH))[t] = f;
    }
    ((uint2*)(g_Bh + (size_t)j * CHP))[t] = h;
}

// ---------------- knull: filler so GEMM is launch #4 for ncu ----------------
__global__ void knull() {
    if (threadIdx.x == 0) g_bar = 0u;   // redundant re-zero
}

// ---------------- K2: HMMA fp16 GEMM 128x192 (round-11 exact, 143.8us) ----------------
#define STG 57344
#define GEMM_SMEM (2 * STG)

__global__ __launch_bounds__(256, 1) void kgemm_mma(const float* __restrict__ x,
                                                    const float* __restrict__ gamma,
                                                    const float* __restrict__ beta,
                                                    float* __restrict__ sim, int N) {
    extern __shared__ char smem[];
    const uint32_t sb = smem_u32(smem);

    int tid = threadIdx.x;
    int lane = tid & 31, warp = tid >> 5;        // 8 warps
    int wm = warp & 3, wn = warp >> 2;           // 4 M x 2 N
    int rowBase = (int)blockIdx.x * 128;

    int arow = tid >> 4, aq = tid & 15;          // A: rows arow + r*16 (r<8)
    int brow = tid >> 3, bq = tid & 7;           // B: rows brow + r*32 (r<6)

    float mu[8], Pv[8], Qv[8];
    #pragma unroll
    for (int r = 0; r < 8; r++) {
        int gr = rowBase + arow + r * 16;
        if (gr < N) { mu[r] = g_mu[gr]; Pv[r] = g_P[gr]; Qv[r] = g_Q[gr]; }
        else        { mu[r] = 0.f; Pv[r] = 0.f; Qv[r] = 0.f; }
    }

    float acc[2][12][4];
    #pragma unroll
    for (int t = 0; t < 2; t++)
        #pragma unroll
        for (int nt = 0; nt < 12; nt++)
            #pragma unroll
            for (int i = 0; i < 4; i++) acc[t][nt][i] = 0.f;

    float4 xr[8], g4, b4;

    auto convertA = [&](uint32_t st) {
        #pragma unroll
        for (int r = 0; r < 8; r++) {
            float yx = (xr[r].x - mu[r]) * Pv[r] * g4.x + Qv[r] * b4.x;
            float yy = (xr[r].y - mu[r]) * Pv[r] * g4.y + Qv[r] * b4.y;
            float yz = (xr[r].z - mu[r]) * Pv[r] * g4.z + Qv[r] * b4.z;
            float yw = (xr[r].w - mu[r]) * Pv[r] * g4.w + Qv[r] * b4.w;
            unsigned h0, l0, h1, l1;
            split2h(yx, yy, h0, l0);
            split2h(yz, yw, h1, l1);
            int row = arow + r * 16;
            uint32_t off = (uint32_t)(row * 128 + ((aq * 8) ^ ((row & 7) << 4)));
            asm volatile("st.shared.v2.b32 [%0], {%1,%2};" :: "r"(st + off), "r"(h0), "r"(h1));
            asm volatile("st.shared.v2.b32 [%0], {%1,%2};" :: "r"(st + 16384 + off), "r"(l0), "r"(l1));
        }
    };

    auto mma_step = [&](int s, uint32_t sAhi, uint32_t sAlo, uint32_t sB) {
        uint32_t ahi[2][4], alo[2][4], bh[6][4];
        uint32_t kb = (uint32_t)(s * 32 + ((lane >> 4) & 1) * 16);
        #pragma unroll
        for (int t = 0; t < 2; t++) {
            int row = wm * 32 + t * 16 + (lane & 15);
            uint32_t off = (uint32_t)(row * 128) + (kb ^ ((uint32_t)(row & 7) << 4));
            LDMX4(ahi[t][0], ahi[t][1], ahi[t][2], ahi[t][3], sAhi + off);
            LDMX4(alo[t][0], alo[t][1], alo[t][2], alo[t][3], sAlo + off);
        }
        #pragma unroll
        for (int g = 0; g < 6; g++) {
            int row = wn * 96 + g * 16 + (lane & 15);
            uint32_t off = (uint32_t)(row * 128) + (kb ^ ((uint32_t)(row & 7) << 4));
            LDMX4(bh[g][0], bh[g][1], bh[g][2], bh[g][3], sB + off);
        }
        #pragma unroll
        for (int t = 0; t < 2; t++)
            #pragma unroll
            for (int g = 0; g < 6; g++)
                #pragma unroll
                for (int h = 0; h < 2; h++) {
                    int nt = g * 2 + h;
                    MMA16816H(acc[t][nt], ahi[t], bh[g][h], bh[g][h + 2]);
                    MMA16816H(acc[t][nt], alo[t], bh[g][h], bh[g][h + 2]);
                }
    };

    // ======== prologue ========
    {
        uint32_t sB = sb + 32768;
        #pragma unroll
        for (int r = 0; r < 6; r++) {
            int row = brow + r * 32;
            uint32_t off = (uint32_t)(row * 128 + ((bq * 16) ^ ((row & 7) << 4)));
            CP_ASYNC16(sB + off, (const char*)(g_Bh + (size_t)row * CHP) + bq * 16);
        }
        asm volatile("cp.async.commit_group;" ::: "memory");

        g4 = ((const float4*)gamma)[aq];
        b4 = ((const float4*)beta)[aq];
        #pragma unroll
        for (int r = 0; r < 8; r++) {
            int gr = rowBase + arow + r * 16;
            xr[r] = (gr < N) ? ((const float4*)(x + (size_t)gr * CH))[aq]
                             : make_float4(0, 0, 0, 0);
        }
        convertA(sb);

        uint32_t nB = sb + STG + 32768;
        #pragma unroll
        for (int r = 0; r < 6; r++) {
            int row = brow + r * 32;
            uint32_t off = (uint32_t)(row * 128 + ((bq * 16) ^ ((row & 7) << 4)));
            CP_ASYNC16(nB + off, (const char*)(g_Bh + (size_t)row * CHP + 64) + bq * 16);
        }
        asm volatile("cp.async.commit_group;" ::: "memory");

        g4 = ((const float4*)gamma)[16 + aq];
        b4 = ((const float4*)beta)[16 + aq];
        #pragma unroll
        for (int r = 0; r < 8; r++) {
            int gr = rowBase + arow + r * 16;
            xr[r] = (gr < N) ? ((const float4*)(x + (size_t)gr * CH))[16 + aq]
                             : make_float4(0, 0, 0, 0);
        }

        asm volatile("cp.async.wait_group 1;" ::: "memory");
        __syncthreads();
    }

    // ======== main loop ========
    for (int c = 0; c < 12; c++) {
        uint32_t st = sb + (uint32_t)(c & 1) * STG;
        uint32_t sAhi = st, sAlo = st + 16384, sB = st + 32768;

        mma_step(0, sAhi, sAlo, sB);

        if (c < 11) {
            convertA(sb + (uint32_t)((c + 1) & 1) * STG);
            if (c < 10) {
                int c0 = (c + 2) * 64;
                bool kin = (c0 + aq * 4) < CH;
                g4 = kin ? ((const float4*)gamma)[(c0 >> 2) + aq] : make_float4(0, 0, 0, 0);
                b4 = kin ? ((const float4*)beta)[(c0 >> 2) + aq]  : make_float4(0, 0, 0, 0);
                #pragma unroll
                for (int r = 0; r < 8; r++) {
                    int gr = rowBase + arow + r * 16;
                    xr[r] = (kin && gr < N) ? ((const float4*)(x + (size_t)gr * CH))[(c0 >> 2) + aq]
                                            : make_float4(0, 0, 0, 0);
                }
            }
        }

        if (c != 11) {
            mma_step(1, sAhi, sAlo, sB);
            mma_step(2, sAhi, sAlo, sB);
            mma_step(3, sAhi, sAlo, sB);
        }

        if (c < 11) asm volatile("cp.async.wait_group 0;" ::: "memory");
        __syncthreads();

        if (c < 10) {
            int c0 = (c + 2) * 64;
            uint32_t nB = sb + (uint32_t)(c & 1) * STG + 32768;
            #pragma unroll
            for (int r = 0; r < 6; r++) {
                int row = brow + r * 32;
                uint32_t off = (uint32_t)(row * 128 + ((bq * 16) ^ ((row & 7) << 4)));
                CP_ASYNC16(nB + off, (const char*)(g_Bh + (size_t)row * CHP + c0) + bq * 16);
            }
            asm volatile("cp.async.commit_group;" ::: "memory");
        }
    }

    // ======== epilogue ========
    #pragma unroll
    for (int t = 0; t < 2; t++) {
        int r0 = rowBase + wm * 32 + t * 16 + (lane >> 2);
        #pragma unroll
        for (int nt = 0; nt < 12; nt++) {
            int cc = wn * 96 + nt * 8 + ((lane & 3) << 1);
            if (cc < JN) {
                if (r0 < N)
                    *(float2*)(sim + (size_t)r0 * JN + cc) =
                        make_float2(acc[t][nt][0], acc[t][nt][1]);
                if (r0 + 8 < N)
                    *(float2*)(sim + (size_t)(r0 + 8) * JN + cc) =
                        make_float2(acc[t][nt][2], acc[t][nt][3]);
            }
        }
    }
}

// ---------------- K3: kpix — argmax + e + class sums + IN-BLOCK exact fixup ----------------
#define KPIX_SMEM (64 * JN * 4)
__global__ __launch_bounds__(128) void kpix(const float* __restrict__ sim,
                                            const int* __restrict__ gt,
                                            const float* __restrict__ x,
                                            const float* __restrict__ gamma,
                                            const float* __restrict__ beta,
                                            float* __restrict__ pred_out, int N) {
    extern __shared__ float srow[];
    __shared__ float sS[KC];
    __shared__ int sC[KC];
    __shared__ int sFixN[64];
    __shared__ unsigned sFixM[64];
    __shared__ int sFixCnt;
    if (threadIdx.x < KC) { sS[threadIdx.x] = 0.f; sC[threadIdx.x] = 0; }
    if (threadIdx.x == 0) sFixCnt = 0;
    int base = blockIdx.x * 64;
    int npix = min(64, N - base);
    if (npix <= 0) return;
    int n4 = npix * JN / 2;
    const float2* src = (const float2*)(sim + (size_t)base * JN);
    float2* dst = (float2*)srow;
    for (int i = threadIdx.x; i < n4; i += 128) dst[i] = src[i];
    __syncthreads();
    if (threadIdx.x < npix) {
        int n = base + threadIdx.x;
        const float* row = srow + threadIdx.x * JN;
        int g = gt[n];
        float mk[KC];
        float best = -3.4e38f; int bk = 0;
        #pragma unroll
        for (int k = 0; k < KC; k++) {
            float m0 = row[k];
            #pragma unroll
            for (int m = 1; m < MP; m++) m0 = fmaxf(m0, row[m * KC + k]);
            mk[k] = m0;
            if (m0 > best) { best = m0; bk = k; }
        }
        pred_out[n] = (float)bk;
        unsigned mask = 0; int ccount = 0;
        float thr = best - TAU;
        #pragma unroll
        for (int k = 0; k < KC; k++)
            if (mk[k] > thr) { mask |= (1u << k); ccount++; }
        if (ccount > 1) {
            int idx = atomicAdd(&sFixCnt, 1);
            sFixN[idx] = n;
            sFixM[idx] = mask;
        }
        float se = 0.f;
        #pragma unroll
        for (int m = 0; m < MP; m++) {
            float e = expf(row[m * KC + g] * 20.0f);
            g_e[(size_t)n * MP + m] = e;
            se += e;
        }
        atomicAdd(&sS[g], se);
        atomicAdd(&sC[g], 1);
    }
    __syncthreads();
    if (threadIdx.x < KC) {
        if (sS[threadIdx.x] != 0.f) atomicAdd(&g_S[threadIdx.x], sS[threadIdx.x]);
        if (sC[threadIdx.x] != 0)   atomicAdd(&g_cnt[threadIdx.x], sC[threadIdx.x]);
    }
    // ---- in-block exact fp32 fixup: warp-cooperative over flagged pixels ----
    int cnt = sFixCnt;
    int lane = threadIdx.x & 31, warp = threadIdx.x >> 5;
    for (int i = warp; i < cnt; i += 4) {
        int n = sFixN[i];
        unsigned mask = sFixM[i];
        float mu = g_mu[n], P = g_P[n], Q = g_Q[n];
        const float4* xr = (const float4*)(x + (size_t)n * CH);
        float4 xn[6];
        #pragma unroll
        for (int q = 0; q < 6; q++) {
            int idx = q * 32 + lane;
            if (idx < 180) {
                float4 v = xr[idx];
                float4 g4 = ((const float4*)gamma)[idx];
                float4 b4 = ((const float4*)beta)[idx];
                xn[q].x = (v.x - mu) * P * g4.x + Q * b4.x;
                xn[q].y = (v.y - mu) * P * g4.y + Q * b4.y;
                xn[q].z = (v.z - mu) * P * g4.z + Q * b4.z;
                xn[q].w = (v.w - mu) * P * g4.w + Q * b4.w;
            } else xn[q] = make_float4(0, 0, 0, 0);
        }
        float best = -3.4e38f; int bk = 0;
        for (int k = 0; k < KC; k++) {
            if (!((mask >> k) & 1u)) continue;
            float smax = -3.4e38f;
            for (int m = 0; m < MP; m++) {
                const float4* pr = (const float4*)(g_Bf + (size_t)(m * KC + k) * CH);
                float d = 0.f;
                #pragma unroll
                for (int q = 0; q < 6; q++) {
                    int idx = q * 32 + lane;
                    if (idx < 180) {
                        float4 p = pr[idx];
                        d += xn[q].x * p.x + xn[q].y * p.y + xn[q].z * p.z + xn[q].w * p.w;
                    }
                }
                d = warpReduceSum(d);
                smax = fmaxf(smax, d);
            }
            if (smax > best) { best = smax; bk = k; }  // ascending k, strict > = first-occurrence
        }
        if (lane == 0) pred_out[n] = (float)bk;
    }
}

// ---------------- K4: fused sinkhorn (kT0 + kCT1 + kCT2 + kCQ, grid-barriered) ----------------
__device__ __forceinline__ void gridbar(unsigned target) {
    __threadfence();
    __syncthreads();
    if (threadIdx.x == 0) {
        atomicAdd(&g_bar, 1u);
        while (*((volatile unsigned*)&g_bar) < target) {}
    }
    __syncthreads();
}

__global__ __launch_bounds__(256) void ksink(const int* __restrict__ gt,
                                             float* __restrict__ qout, int N) {
    __shared__ float sr[JN];
    __shared__ float sT[JN];
    int tid = threadIdx.x;
    int n = blockIdx.x * 256 + tid;
    bool act = (n < N);
    int g = act ? gt[n] : 0;
    float e[MP];
    float ns = 1.f, c = 0.f;
    if (act) {
        #pragma unroll
        for (int m = 0; m < MP; m++) e[m] = g_e[(size_t)n * MP + m];
        ns = fmaxf((float)g_cnt[g], 1.f);
        c = 1.f / fmaxf(g_S[g], 1e-12f);          // c0
    }

    // ---- phase 0: T1 = sum c0*e ----
    for (int j = tid; j < JN; j += 256) sT[j] = 0.f;
    __syncthreads();
    if (act) {
        #pragma unroll
        for (int m = 0; m < MP; m++) atomicAdd(&sT[g * MP + m], c * e[m]);
    }
    __syncthreads();
    for (int j = tid; j < JN; j += 256)
        if (sT[j] != 0.f) atomicAdd(&g_T3[0][j], sT[j]);
    gridbar(gridDim.x);

    // ---- phase 1: r1, c1, T2 ----
    if (tid < JN) {
        float r = 1.f / (fmaxf(__ldcg(&g_T3[0][tid]), 1e-12f) * (float)MP);
        sr[tid] = r;
    }
    __syncthreads();
    for (int j = tid; j < JN; j += 256) sT[j] = 0.f;
    __syncthreads();
    if (act) {
        float V = 0.f;
        #pragma unroll
        for (int m = 0; m < MP; m++) V += e[m] * sr[g * MP + m];
        c = c / (fmaxf(c * V, 1e-12f) * ns);
        #pragma unroll
        for (int m = 0; m < MP; m++) atomicAdd(&sT[g * MP + m], c * e[m]);
    }
    __syncthreads();
    for (int j = tid; j < JN; j += 256)
        if (sT[j] != 0.f) atomicAdd(&g_T3[1][j], sT[j]);
    gridbar(2u * gridDim.x);

    // ---- phase 2: r2, c2, T3 ----
    if (tid < JN) {
        float r = 1.f / (fmaxf(__ldcg(&g_T3[0][tid]), 1e-12f) * (float)MP);
        r = r / (fmaxf(r * __ldcg(&g_T3[1][tid]), 1e-12f) * (float)MP);
        sr[tid] = r;
    }
    __syncthreads();
    for (int j = tid; j < JN; j += 256) sT[j] = 0.f;
    __syncthreads();
    if (act) {
        float V = 0.f;
        #pragma unroll
        for (int m = 0; m < MP; m++) V += e[m] * sr[g * MP + m];
        c = c / (fmaxf(c * V, 1e-12f) * ns);
        #pragma unroll
        for (int m = 0; m < MP; m++) atomicAdd(&sT[g * MP + m], c * e[m]);
    }
    __syncthreads();
    for (int j = tid; j < JN; j += 256)
        if (sT[j] != 0.f) atomicAdd(&g_T3[2][j], sT[j]);
    gridbar(3u * gridDim.x);

    // ---- phase 3: r3, c3, q scatter ----
    if (tid < JN) {
        float r = 1.f / (fmaxf(__ldcg(&g_T3[0][tid]), 1e-12f) * (float)MP);
        r = r / (fmaxf(r * __ldcg(&g_T3[1][tid]), 1e-12f) * (float)MP);
        r = r / (fmaxf(r * __ldcg(&g_T3[2][tid]), 1e-12f) * (float)MP);
        sr[tid] = r;
    }
    __syncthreads();
    if (act) {
        float V = 0.f;
        #pragma unroll
        for (int m = 0; m < MP; m++) V += e[m] * sr[g * MP + m];
        c = c / (fmaxf(c * V, 1e-12f) * ns);
        float cs = c * ns;
        size_t base = ((size_t)g * N + n) * MP;
        #pragma unroll
        for (int m = 0; m < MP; m++)
            qout[base + m] = cs * e[m] * sr[g * MP + m];
    }
}

// ---------------- launch ----------------
extern "C" void kernel_launch(void* const* d_in, const int* in_sizes, int n_in,
                              void* d_out, int out_size) {
    const float* x     = (const float*)d_in[0];
    const int*   gt    = (const int*)d_in[1];
    const float* gamma = (const float*)d_in[2];
    const float* beta  = (const float*)d_in[3];
    const float* proto = (const float*)d_in[4];
    int N = in_sizes[0] / CH;

    float* out  = (float*)d_out;
    float* sim  = out;
    float* q    = out + (size_t)N * JN;
    float* pred = out + 2 * (size_t)N * JN;

    cudaFuncSetAttribute(kgemm_mma, cudaFuncAttributeMaxDynamicSharedMemorySize, GEMM_SMEM);
    cudaFuncSetAttribute(kpix, cudaFuncAttributeMaxDynamicSharedMemorySize, KPIX_SMEM);

    kprotoB<<<JN + 1, 192>>>(proto);
    kstats<<<(N + 7) / 8, 256>>>(x, gamma, beta, N);
    knull<<<1, 32>>>();   // filler so kgemm is launch #4 (the one ncu captures)
    kgemm_mma<<<(N + 127) / 128, 256, GEMM_SMEM>>>(x, gamma, beta, sim, N);
    kpix<<<(N + 63) / 64, 128, KPIX_SMEM>>>(sim, gt, x, gamma, beta, pred, N);

    cudaMemsetAsync(q, 0, (size_t)N * JN * sizeof(float));
    ksink<<<(N + 255) / 256, 256>>>(gt, q, N);
}

// round 15
// speedup vs baseline: 1.0165x; 1.0001x over previous
#include <cuda_runtime.h>
#include <cuda_fp16.h>
#include <math.h>
#include <stdint.h>

#define KC 19
#define MP 10
#define CH 720
#define CHP 768
#define JN 190
#define JP 192
#define NMAX 65536
#define TAU 6e-4f

// ---------------- scratch ----------------
__device__ __align__(256) __half g_Bh[JP * CHP];
__device__ __align__(256) float g_Bf[(size_t)JN * CH];
__device__ float g_mu[NMAX];
__device__ float g_P[NMAX];
__device__ float g_Q[NMAX];
__device__ float g_e[(size_t)NMAX * MP];
__device__ float g_S[KC];
__device__ int   g_cnt[KC];
__device__ float g_T3[3][JN];   // [0]=T1 (c0-weighted), [1]=T2, [2]=T3
__device__ unsigned g_bar;

// ---------------- helpers ----------------
__device__ __forceinline__ uint32_t smem_u32(const void* p) {
    uint32_t a;
    asm("{ .reg .u64 t; cvta.to.shared.u64 t, %1; cvt.u32.u64 %0, t; }" : "=r"(a) : "l"(p));
    return a;
}
__device__ __forceinline__ float warpReduceSum(float v) {
    #pragma unroll
    for (int o = 16; o > 0; o >>= 1) v += __shfl_xor_sync(0xffffffffu, v, o);
    return v;
}
__device__ __forceinline__ float blockReduceSum(float v, float* sh) {
    __syncthreads();
    v = warpReduceSum(v);
    int lane = threadIdx.x & 31, w = threadIdx.x >> 5;
    if (lane == 0) sh[w] = v;
    __syncthreads();
    int nw = (blockDim.x + 31) >> 5;
    v = (threadIdx.x < nw) ? sh[threadIdx.x] : 0.f;
    if (w == 0) { v = warpReduceSum(v); if (lane == 0) sh[0] = v; }
    __syncthreads();
    return sh[0];
}
__device__ __forceinline__ void split2h(float a0, float a1, unsigned& h, unsigned& l) {
    __half2 hh = __floats2half2_rn(a0, a1);
    float2 hf = __half22float2(hh);
    __half2 ll = __floats2half2_rn(a0 - hf.x, a1 - hf.y);
    h = *(unsigned*)&hh;
    l = *(unsigned*)&ll;
}

#define LDMX4(r0, r1, r2, r3, addr) \
    asm volatile("ldmatrix.sync.aligned.m8n8.x4.shared.b16 {%0,%1,%2,%3}, [%4];" \
                 : "=r"(r0), "=r"(r1), "=r"(r2), "=r"(r3) : "r"(addr))

#define MMA16816H(d, a, b0, b1) \
    asm volatile("mma.sync.aligned.m16n8k16.row.col.f32.f16.f16.f32 " \
                 "{%0,%1,%2,%3}, {%4,%5,%6,%7}, {%8,%9}, {%0,%1,%2,%3};" \
                 : "+f"((d)[0]), "+f"((d)[1]), "+f"((d)[2]), "+f"((d)[3]) \
                 : "r"((a)[0]), "r"((a)[1]), "r"((a)[2]), "r"((a)[3]), "r"(b0), "r"(b1))

#define CP_ASYNC16(dst, src) \
    asm volatile("cp.async.ca.shared.global [%0], [%1], 16;" \
                 :: "r"(dst), "l"(src) : "memory")

// ---------------- K0: warp-per-row stats ----------------
__global__ __launch_bounds__(256) void kstats(const float* __restrict__ x,
                                              const float* __restrict__ gamma,
                                              const float* __restrict__ beta, int N) {
    int warp = threadIdx.x >> 5, lane = threadIdx.x & 31;
    int n = blockIdx.x * 8 + warp;
    if (n >= N) return;
    const float4* xr = (const float4*)(x + (size_t)n * CH);
    float4 v[6];
    float s = 0.f, sq = 0.f;
    #pragma unroll
    for (int i = 0; i < 6; i++) {
        int idx = i * 32 + lane;
        if (idx < 180) {
            v[i] = xr[idx];
            s += v[i].x + v[i].y + v[i].z + v[i].w;
            sq += v[i].x * v[i].x + v[i].y * v[i].y + v[i].z * v[i].z + v[i].w * v[i].w;
        } else v[i] = make_float4(0, 0, 0, 0);
    }
    s = warpReduceSum(s);
    sq = warpReduceSum(sq);
    float mu = s * (1.f / (float)CH);
    float rs = rsqrtf(sq * (1.f / (float)CH) - mu * mu + 1e-5f);
    float yn = 0.f;
    #pragma unroll
    for (int i = 0; i < 6; i++) {
        int idx = i * 32 + lane;
        if (idx < 180) {
            float4 g4 = ((const float4*)gamma)[idx];
            float4 b4 = ((const float4*)beta)[idx];
            float a = (v[i].x - mu) * rs * g4.x + b4.x;
            float b = (v[i].y - mu) * rs * g4.y + b4.y;
            float c = (v[i].z - mu) * rs * g4.z + b4.z;
            float d = (v[i].w - mu) * rs * g4.w + b4.w;
            yn += a * a + b * b + c * c + d * d;
        }
    }
    yn = warpReduceSum(yn);
    float inv = 1.f / fmaxf(sqrtf(yn), 1e-12f);
    if (lane == 0) { g_mu[n] = mu; g_P[n] = rs * inv; g_Q[n] = inv; }
}

// ---------------- K1: normalize prototypes (fp16 + fp32) + init ----------------
__global__ __launch_bounds__(192) void kprotoB(const float* __restrict__ proto) {
    int p = blockIdx.x;
    int t = threadIdx.x;
    __shared__ float sh[32];
    if (p == JN) {
        ((uint2*)(g_Bh + (size_t)190 * CHP))[t] = make_uint2(0u, 0u);
        ((uint2*)(g_Bh + (size_t)191 * CHP))[t] = make_uint2(0u, 0u);
        if (t < KC) { g_S[t] = 0.f; g_cnt[t] = 0; }
        if (t == 0) g_bar = 0u;
        for (int j = t; j < 3 * JN; j += 192) ((float*)g_T3)[j] = 0.f;
        return;
    }
    int k = p / MP, m = p % MP;
    int j = m * KC + k;
    const float4* pr = (const float4*)(proto + (size_t)p * CH);
    float4 v = make_float4(0, 0, 0, 0);
    float ss = 0.f;
    if (t < 180) {
        v = pr[t];
        ss = v.x * v.x + v.y * v.y + v.z * v.z + v.w * v.w;
    }
    ss = blockReduceSum(ss, sh);
    float inv = 1.f / fmaxf(sqrtf(ss), 1e-12f);
    uint2 h = make_uint2(0u, 0u);
    if (t < 180) {
        float4 f = make_float4(v.x * inv, v.y * inv, v.z * inv, v.w * inv);
        __half2 h0 = __floats2half2_rn(f.x, f.y);
        __half2 h1 = __floats2half2_rn(f.z, f.w);
        h.x = *(unsigned*)&h0;
        h.y = *(unsigned*)&h1;
        ((float4*)(g_Bf + (size_t)j * CH))[t] = f;
    }
    ((uint2*)(g_Bh + (size_t)j * CHP))[t] = h;
}

// ---------------- K2: HMMA fp16 GEMM 128x192 (round-11 exact, 143.3us) ----------------
#define STG 57344
#define GEMM_SMEM (2 * STG)

__global__ __launch_bounds__(256, 1) void kgemm_mma(const float* __restrict__ x,
                                                    const float* __restrict__ gamma,
                                                    const float* __restrict__ beta,
                                                    float* __restrict__ sim, int N) {
    extern __shared__ char smem[];
    const uint32_t sb = smem_u32(smem);

    int tid = threadIdx.x;
    int lane = tid & 31, warp = tid >> 5;        // 8 warps
    int wm = warp & 3, wn = warp >> 2;           // 4 M x 2 N
    int rowBase = (int)blockIdx.x * 128;

    int arow = tid >> 4, aq = tid & 15;          // A: rows arow + r*16 (r<8)
    int brow = tid >> 3, bq = tid & 7;           // B: rows brow + r*32 (r<6)

    float mu[8], Pv[8], Qv[8];
    #pragma unroll
    for (int r = 0; r < 8; r++) {
        int gr = rowBase + arow + r * 16;
        if (gr < N) { mu[r] = g_mu[gr]; Pv[r] = g_P[gr]; Qv[r] = g_Q[gr]; }
        else        { mu[r] = 0.f; Pv[r] = 0.f; Qv[r] = 0.f; }
    }

    float acc[2][12][4];
    #pragma unroll
    for (int t = 0; t < 2; t++)
        #pragma unroll
        for (int nt = 0; nt < 12; nt++)
            #pragma unroll
            for (int i = 0; i < 4; i++) acc[t][nt][i] = 0.f;

    float4 xr[8], g4, b4;

    auto convertA = [&](uint32_t st) {
        #pragma unroll
        for (int r = 0; r < 8; r++) {
            float yx = (xr[r].x - mu[r]) * Pv[r] * g4.x + Qv[r] * b4.x;
            float yy = (xr[r].y - mu[r]) * Pv[r] * g4.y + Qv[r] * b4.y;
            float yz = (xr[r].z - mu[r]) * Pv[r] * g4.z + Qv[r] * b4.z;
            float yw = (xr[r].w - mu[r]) * Pv[r] * g4.w + Qv[r] * b4.w;
            unsigned h0, l0, h1, l1;
            split2h(yx, yy, h0, l0);
            split2h(yz, yw, h1, l1);
            int row = arow + r * 16;
            uint32_t off = (uint32_t)(row * 128 + ((aq * 8) ^ ((row & 7) << 4)));
            asm volatile("st.shared.v2.b32 [%0], {%1,%2};" :: "r"(st + off), "r"(h0), "r"(h1));
            asm volatile("st.shared.v2.b32 [%0], {%1,%2};" :: "r"(st + 16384 + off), "r"(l0), "r"(l1));
        }
    };

    auto mma_step = [&](int s, uint32_t sAhi, uint32_t sAlo, uint32_t sB) {
        uint32_t ahi[2][4], alo[2][4], bh[6][4];
        uint32_t kb = (uint32_t)(s * 32 + ((lane >> 4) & 1) * 16);
        #pragma unroll
        for (int t = 0; t < 2; t++) {
            int row = wm * 32 + t * 16 + (lane & 15);
            uint32_t off = (uint32_t)(row * 128) + (kb ^ ((uint32_t)(row & 7) << 4));
            LDMX4(ahi[t][0], ahi[t][1], ahi[t][2], ahi[t][3], sAhi + off);
            LDMX4(alo[t][0], alo[t][1], alo[t][2], alo[t][3], sAlo + off);
        }
        #pragma unroll
        for (int g = 0; g < 6; g++) {
            int row = wn * 96 + g * 16 + (lane & 15);
            uint32_t off = (uint32_t)(row * 128) + (kb ^ ((uint32_t)(row & 7) << 4));
            LDMX4(bh[g][0], bh[g][1], bh[g][2], bh[g][3], sB + off);
        }
        #pragma unroll
        for (int t = 0; t < 2; t++)
            #pragma unroll
            for (int g = 0; g < 6; g++)
                #pragma unroll
                for (int h = 0; h < 2; h++) {
                    int nt = g * 2 + h;
                    MMA16816H(acc[t][nt], ahi[t], bh[g][h], bh[g][h + 2]);
                    MMA16816H(acc[t][nt], alo[t], bh[g][h], bh[g][h + 2]);
                }
    };

    // ======== prologue ========
    {
        uint32_t sB = sb + 32768;
        #pragma unroll
        for (int r = 0; r < 6; r++) {
            int row = brow + r * 32;
            uint32_t off = (uint32_t)(row * 128 + ((bq * 16) ^ ((row & 7) << 4)));
            CP_ASYNC16(sB + off, (const char*)(g_Bh + (size_t)row * CHP) + bq * 16);
        }
        asm volatile("cp.async.commit_group;" ::: "memory");

        g4 = ((const float4*)gamma)[aq];
        b4 = ((const float4*)beta)[aq];
        #pragma unroll
        for (int r = 0; r < 8; r++) {
            int gr = rowBase + arow + r * 16;
            xr[r] = (gr < N) ? ((const float4*)(x + (size_t)gr * CH))[aq]
                             : make_float4(0, 0, 0, 0);
        }
        convertA(sb);

        uint32_t nB = sb + STG + 32768;
        #pragma unroll
        for (int r = 0; r < 6; r++) {
            int row = brow + r * 32;
            uint32_t off = (uint32_t)(row * 128 + ((bq * 16) ^ ((row & 7) << 4)));
            CP_ASYNC16(nB + off, (const char*)(g_Bh + (size_t)row * CHP + 64) + bq * 16);
        }
        asm volatile("cp.async.commit_group;" ::: "memory");

        g4 = ((const float4*)gamma)[16 + aq];
        b4 = ((const float4*)beta)[16 + aq];
        #pragma unroll
        for (int r = 0; r < 8; r++) {
            int gr = rowBase + arow + r * 16;
            xr[r] = (gr < N) ? ((const float4*)(x + (size_t)gr * CH))[16 + aq]
                             : make_float4(0, 0, 0, 0);
        }

        asm volatile("cp.async.wait_group 1;" ::: "memory");
        __syncthreads();
    }

    // ======== main loop ========
    for (int c = 0; c < 12; c++) {
        uint32_t st = sb + (uint32_t)(c & 1) * STG;
        uint32_t sAhi = st, sAlo = st + 16384, sB = st + 32768;

        mma_step(0, sAhi, sAlo, sB);

        if (c < 11) {
            convertA(sb + (uint32_t)((c + 1) & 1) * STG);
            if (c < 10) {
                int c0 = (c + 2) * 64;
                bool kin = (c0 + aq * 4) < CH;
                g4 = kin ? ((const float4*)gamma)[(c0 >> 2) + aq] : make_float4(0, 0, 0, 0);
                b4 = kin ? ((const float4*)beta)[(c0 >> 2) + aq]  : make_float4(0, 0, 0, 0);
                #pragma unroll
                for (int r = 0; r < 8; r++) {
                    int gr = rowBase + arow + r * 16;
                    xr[r] = (kin && gr < N) ? ((const float4*)(x + (size_t)gr * CH))[(c0 >> 2) + aq]
                                            : make_float4(0, 0, 0, 0);
                }
            }
        }

        if (c != 11) {
            mma_step(1, sAhi, sAlo, sB);
            mma_step(2, sAhi, sAlo, sB);
            mma_step(3, sAhi, sAlo, sB);
        }

        if (c < 11) asm volatile("cp.async.wait_group 0;" ::: "memory");
        __syncthreads();

        if (c < 10) {
            int c0 = (c + 2) * 64;
            uint32_t nB = sb + (uint32_t)(c & 1) * STG + 32768;
            #pragma unroll
            for (int r = 0; r < 6; r++) {
                int row = brow + r * 32;
                uint32_t off = (uint32_t)(row * 128 + ((bq * 16) ^ ((row & 7) << 4)));
                CP_ASYNC16(nB + off, (const char*)(g_Bh + (size_t)row * CHP + c0) + bq * 16);
            }
            asm volatile("cp.async.commit_group;" ::: "memory");
        }
    }

    // ======== epilogue ========
    #pragma unroll
    for (int t = 0; t < 2; t++) {
        int r0 = rowBase + wm * 32 + t * 16 + (lane >> 2);
        #pragma unroll
        for (int nt = 0; nt < 12; nt++) {
            int cc = wn * 96 + nt * 8 + ((lane & 3) << 1);
            if (cc < JN) {
                if (r0 < N)
                    *(float2*)(sim + (size_t)r0 * JN + cc) =
                        make_float2(acc[t][nt][0], acc[t][nt][1]);
                if (r0 + 8 < N)
                    *(float2*)(sim + (size_t)(r0 + 8) * JN + cc) =
                        make_float2(acc[t][nt][2], acc[t][nt][3]);
            }
        }
    }
}

// ---------------- K3: kpix — argmax + e + class sums + in-block exact fixup ----------------
#define KPIX_SMEM (64 * JN * 4)
__global__ __launch_bounds__(128) void kpix(const float* __restrict__ sim,
                                            const int* __restrict__ gt,
                                            const float* __restrict__ x,
                                            const float* __restrict__ gamma,
                                            const float* __restrict__ beta,
                                            float* __restrict__ pred_out, int N) {
    extern __shared__ float srow[];
    __shared__ float sS[KC];
    __shared__ int sC[KC];
    __shared__ int sFixN[64];
    __shared__ unsigned sFixM[64];
    __shared__ int sFixCnt;
    if (threadIdx.x < KC) { sS[threadIdx.x] = 0.f; sC[threadIdx.x] = 0; }
    if (threadIdx.x == 0) sFixCnt = 0;
    int base = blockIdx.x * 64;
    int npix = min(64, N - base);
    if (npix <= 0) return;
    int n4 = npix * JN / 2;
    const float2* src = (const float2*)(sim + (size_t)base * JN);
    float2* dst = (float2*)srow;
    for (int i = threadIdx.x; i < n4; i += 128) dst[i] = src[i];
    __syncthreads();
    if (threadIdx.x < npix) {
        int n = base + threadIdx.x;
        const float* row = srow + threadIdx.x * JN;
        int g = gt[n];
        float mk[KC];
        float best = -3.4e38f; int bk = 0;
        #pragma unroll
        for (int k = 0; k < KC; k++) {
            float m0 = row[k];
            #pragma unroll
            for (int m = 1; m < MP; m++) m0 = fmaxf(m0, row[m * KC + k]);
            mk[k] = m0;
            if (m0 > best) { best = m0; bk = k; }
        }
        pred_out[n] = (float)bk;
        unsigned mask = 0; int ccount = 0;
        float thr = best - TAU;
        #pragma unroll
        for (int k = 0; k < KC; k++)
            if (mk[k] > thr) { mask |= (1u << k); ccount++; }
        if (ccount > 1) {
            int idx = atomicAdd(&sFixCnt, 1);
            sFixN[idx] = n;
            sFixM[idx] = mask;
        }
        float se = 0.f;
        #pragma unroll
        for (int m = 0; m < MP; m++) {
            float e = expf(row[m * KC + g] * 20.0f);
            g_e[(size_t)n * MP + m] = e;
            se += e;
        }
        atomicAdd(&sS[g], se);
        atomicAdd(&sC[g], 1);
    }
    __syncthreads();
    if (threadIdx.x < KC) {
        if (sS[threadIdx.x] != 0.f) atomicAdd(&g_S[threadIdx.x], sS[threadIdx.x]);
        if (sC[threadIdx.x] != 0)   atomicAdd(&g_cnt[threadIdx.x], sC[threadIdx.x]);
    }
    int cnt = sFixCnt;
    int lane = threadIdx.x & 31, warp = threadIdx.x >> 5;
    for (int i = warp; i < cnt; i += 4) {
        int n = sFixN[i];
        unsigned mask = sFixM[i];
        float mu = g_mu[n], P = g_P[n], Q = g_Q[n];
        const float4* xr = (const float4*)(x + (size_t)n * CH);
        float4 xn[6];
        #pragma unroll
        for (int q = 0; q < 6; q++) {
            int idx = q * 32 + lane;
            if (idx < 180) {
                float4 v = xr[idx];
                float4 g4 = ((const float4*)gamma)[idx];
                float4 b4 = ((const float4*)beta)[idx];
                xn[q].x = (v.x - mu) * P * g4.x + Q * b4.x;
                xn[q].y = (v.y - mu) * P * g4.y + Q * b4.y;
                xn[q].z = (v.z - mu) * P * g4.z + Q * b4.z;
                xn[q].w = (v.w - mu) * P * g4.w + Q * b4.w;
            } else xn[q] = make_float4(0, 0, 0, 0);
        }
        float best = -3.4e38f; int bk = 0;
        for (int k = 0; k < KC; k++) {
            if (!((mask >> k) & 1u)) continue;
            float smax = -3.4e38f;
            for (int m = 0; m < MP; m++) {
                const float4* pr = (const float4*)(g_Bf + (size_t)(m * KC + k) * CH);
                float d = 0.f;
                #pragma unroll
                for (int q = 0; q < 6; q++) {
                    int idx = q * 32 + lane;
                    if (idx < 180) {
                        float4 p = pr[idx];
                        d += xn[q].x * p.x + xn[q].y * p.y + xn[q].z * p.z + xn[q].w * p.w;
                    }
                }
                d = warpReduceSum(d);
                smax = fmaxf(smax, d);
            }
            if (smax > best) { best = smax; bk = k; }
        }
        if (lane == 0) pred_out[n] = (float)bk;
    }
}

// ---------------- K4: fused sinkhorn (grid-barriered) ----------------
__device__ __forceinline__ void gridbar(unsigned target) {
    __threadfence();
    __syncthreads();
    if (threadIdx.x == 0) {
        atomicAdd(&g_bar, 1u);
        while (*((volatile unsigned*)&g_bar) < target) {}
    }
    __syncthreads();
}

__global__ __launch_bounds__(256) void ksink(const int* __restrict__ gt,
                                             float* __restrict__ qout, int N) {
    __shared__ float sr[JN];
    __shared__ float sT[JN];
    int tid = threadIdx.x;
    int n = blockIdx.x * 256 + tid;
    bool act = (n < N);
    int g = act ? gt[n] : 0;
    float e[MP];
    float ns = 1.f, c = 0.f;
    if (act) {
        #pragma unroll
        for (int m = 0; m < MP; m++) e[m] = g_e[(size_t)n * MP + m];
        ns = fmaxf((float)g_cnt[g], 1.f);
        c = 1.f / fmaxf(g_S[g], 1e-12f);          // c0
    }

    // phase 0: T1
    for (int j = tid; j < JN; j += 256) sT[j] = 0.f;
    __syncthreads();
    if (act) {
        #pragma unroll
        for (int m = 0; m < MP; m++) atomicAdd(&sT[g * MP + m], c * e[m]);
    }
    __syncthreads();
    for (int j = tid; j < JN; j += 256)
        if (sT[j] != 0.f) atomicAdd(&g_T3[0][j], sT[j]);
    gridbar(gridDim.x);

    // phase 1: r1, c1, T2
    if (tid < JN) {
        float r = 1.f / (fmaxf(__ldcg(&g_T3[0][tid]), 1e-12f) * (float)MP);
        sr[tid] = r;
    }
    __syncthreads();
    for (int j = tid; j < JN; j += 256) sT[j] = 0.f;
    __syncthreads();
    if (act) {
        float V = 0.f;
        #pragma unroll
        for (int m = 0; m < MP; m++) V += e[m] * sr[g * MP + m];
        c = c / (fmaxf(c * V, 1e-12f) * ns);
        #pragma unroll
        for (int m = 0; m < MP; m++) atomicAdd(&sT[g * MP + m], c * e[m]);
    }
    __syncthreads();
    for (int j = tid; j < JN; j += 256)
        if (sT[j] != 0.f) atomicAdd(&g_T3[1][j], sT[j]);
    gridbar(2u * gridDim.x);

    // phase 2: r2, c2, T3
    if (tid < JN) {
        float r = 1.f / (fmaxf(__ldcg(&g_T3[0][tid]), 1e-12f) * (float)MP);
        r = r / (fmaxf(r * __ldcg(&g_T3[1][tid]), 1e-12f) * (float)MP);
        sr[tid] = r;
    }
    __syncthreads();
    for (int j = tid; j < JN; j += 256) sT[j] = 0.f;
    __syncthreads();
    if (act) {
        float V = 0.f;
        #pragma unroll
        for (int m = 0; m < MP; m++) V += e[m] * sr[g * MP + m];
        c = c / (fmaxf(c * V, 1e-12f) * ns);
        #pragma unroll
        for (int m = 0; m < MP; m++) atomicAdd(&sT[g * MP + m], c * e[m]);
    }
    __syncthreads();
    for (int j = tid; j < JN; j += 256)
        if (sT[j] != 0.f) atomicAdd(&g_T3[2][j], sT[j]);
    gridbar(3u * gridDim.x);

    // phase 3: r3, c3, q scatter
    if (tid < JN) {
        float r = 1.f / (fmaxf(__ldcg(&g_T3[0][tid]), 1e-12f) * (float)MP);
        r = r / (fmaxf(r * __ldcg(&g_T3[1][tid]), 1e-12f) * (float)MP);
        r = r / (fmaxf(r * __ldcg(&g_T3[2][tid]), 1e-12f) * (float)MP);
        sr[tid] = r;
    }
    __syncthreads();
    if (act) {
        float V = 0.f;
        #pragma unroll
        for (int m = 0; m < MP; m++) V += e[m] * sr[g * MP + m];
        c = c / (fmaxf(c * V, 1e-12f) * ns);
        float cs = c * ns;
        size_t base = ((size_t)g * N + n) * MP;
        #pragma unroll
        for (int m = 0; m < MP; m++)
            qout[base + m] = cs * e[m] * sr[g * MP + m];
    }
}

// ---------------- launch (stream fork/join for independent work) ----------------
extern "C" void kernel_launch(void* const* d_in, const int* in_sizes, int n_in,
                              void* d_out, int out_size) {
    const float* x     = (const float*)d_in[0];
    const int*   gt    = (const int*)d_in[1];
    const float* gamma = (const float*)d_in[2];
    const float* beta  = (const float*)d_in[3];
    const float* proto = (const float*)d_in[4];
    int N = in_sizes[0] / CH;

    float* out  = (float*)d_out;
    float* sim  = out;
    float* q    = out + (size_t)N * JN;
    float* pred = out + 2 * (size_t)N * JN;

    static cudaStream_t s1 = nullptr;
    static cudaEvent_t evFork = nullptr, evProto = nullptr, evMemset = nullptr;
    if (!s1) {   // created on the first (uncaptured) correctness call; reused thereafter
        cudaStreamCreateWithFlags(&s1, cudaStreamNonBlocking);
        cudaEventCreateWithFlags(&evFork, cudaEventDisableTiming);
        cudaEventCreateWithFlags(&evProto, cudaEventDisableTiming);
        cudaEventCreateWithFlags(&evMemset, cudaEventDisableTiming);
        cudaFuncSetAttribute(kgemm_mma, cudaFuncAttributeMaxDynamicSharedMemorySize, GEMM_SMEM);
        cudaFuncSetAttribute(kpix, cudaFuncAttributeMaxDynamicSharedMemorySize, KPIX_SMEM);
    }

    // fork: side stream does kprotoB then q-memset while main does kstats / GEMM
    cudaEventRecord(evFork, 0);
    cudaStreamWaitEvent(s1, evFork, 0);

    kprotoB<<<JN + 1, 192, 0, s1>>>(proto);
    cudaEventRecord(evProto, s1);
    cudaMemsetAsync(q, 0, (size_t)N * JN * sizeof(float), s1);
    cudaEventRecord(evMemset, s1);

    kstats<<<(N + 7) / 8, 256>>>(x, gamma, beta, N);

    cudaStreamWaitEvent(0, evProto, 0);     // GEMM needs g_Bh (+ inits)
    kgemm_mma<<<(N + 127) / 128, 256, GEMM_SMEM>>>(x, gamma, beta, sim, N);
    kpix<<<(N + 63) / 64, 128, KPIX_SMEM>>>(sim, gt, x, gamma, beta, pred, N);

    cudaStreamWaitEvent(0, evMemset, 0);    // q must be zeroed before ksink writes
    ksink<<<(N + 255) / 256, 256>>>(gt, q, N);
}

// round 16
// speedup vs baseline: 1.1074x; 1.0894x over previous
#include <cuda_runtime.h>
#include <cuda_fp16.h>
#include <math.h>
#include <stdint.h>

#define KC 19
#define MP 10
#define CH 720
#define CHP 768
#define JN 190
#define JP 192
#define NMAX 65536
#define TAU 6e-4f

// ---------------- scratch ----------------
__device__ __align__(256) __half g_Bh[JP * CHP];
__device__ __align__(256) float g_Bf[(size_t)JN * CH];
__device__ float g_mu[NMAX];
__device__ float g_P[NMAX];
__device__ float g_Q[NMAX];
__device__ float g_e[(size_t)NMAX * MP];
__device__ float g_S[KC];
__device__ int   g_cnt[KC];
__device__ float g_T3[3][JN];   // [0]=T1 (c0-weighted), [1]=T2, [2]=T3
__device__ unsigned g_bar;
__device__ int      g_fixcnt;
__device__ int      g_fixn[NMAX];
__device__ unsigned g_fixmask[NMAX];

// ---------------- helpers ----------------
__device__ __forceinline__ uint32_t smem_u32(const void* p) {
    uint32_t a;
    asm("{ .reg .u64 t; cvta.to.shared.u64 t, %1; cvt.u32.u64 %0, t; }" : "=r"(a) : "l"(p));
    return a;
}
__device__ __forceinline__ float warpReduceSum(float v) {
    #pragma unroll
    for (int o = 16; o > 0; o >>= 1) v += __shfl_xor_sync(0xffffffffu, v, o);
    return v;
}
__device__ __forceinline__ float blockReduceSum(float v, float* sh) {
    __syncthreads();
    v = warpReduceSum(v);
    int lane = threadIdx.x & 31, w = threadIdx.x >> 5;
    if (lane == 0) sh[w] = v;
    __syncthreads();
    int nw = (blockDim.x + 31) >> 5;
    v = (threadIdx.x < nw) ? sh[threadIdx.x] : 0.f;
    if (w == 0) { v = warpReduceSum(v); if (lane == 0) sh[0] = v; }
    __syncthreads();
    return sh[0];
}
__device__ __forceinline__ void split2h(float a0, float a1, unsigned& h, unsigned& l) {
    __half2 hh = __floats2half2_rn(a0, a1);
    float2 hf = __half22float2(hh);
    __half2 ll = __floats2half2_rn(a0 - hf.x, a1 - hf.y);
    h = *(unsigned*)&hh;
    l = *(unsigned*)&ll;
}

#define LDMX4(r0, r1, r2, r3, addr) \
    asm volatile("ldmatrix.sync.aligned.m8n8.x4.shared.b16 {%0,%1,%2,%3}, [%4];" \
                 : "=r"(r0), "=r"(r1), "=r"(r2), "=r"(r3) : "r"(addr))

#define MMA16816H(d, a, b0, b1) \
    asm volatile("mma.sync.aligned.m16n8k16.row.col.f32.f16.f16.f32 " \
                 "{%0,%1,%2,%3}, {%4,%5,%6,%7}, {%8,%9}, {%0,%1,%2,%3};" \
                 : "+f"((d)[0]), "+f"((d)[1]), "+f"((d)[2]), "+f"((d)[3]) \
                 : "r"((a)[0]), "r"((a)[1]), "r"((a)[2]), "r"((a)[3]), "r"(b0), "r"(b1))

#define CP_ASYNC16(dst, src) \
    asm volatile("cp.async.ca.shared.global [%0], [%1], 16;" \
                 :: "r"(dst), "l"(src) : "memory")

// ---------------- K0: warp-per-row stats ----------------
__global__ __launch_bounds__(256) void kstats(const float* __restrict__ x,
                                              const float* __restrict__ gamma,
                                              const float* __restrict__ beta, int N) {
    int warp = threadIdx.x >> 5, lane = threadIdx.x & 31;
    int n = blockIdx.x * 8 + warp;
    if (n >= N) return;
    const float4* xr = (const float4*)(x + (size_t)n * CH);
    float4 v[6];
    float s = 0.f, sq = 0.f;
    #pragma unroll
    for (int i = 0; i < 6; i++) {
        int idx = i * 32 + lane;
        if (idx < 180) {
            v[i] = xr[idx];
            s += v[i].x + v[i].y + v[i].z + v[i].w;
            sq += v[i].x * v[i].x + v[i].y * v[i].y + v[i].z * v[i].z + v[i].w * v[i].w;
        } else v[i] = make_float4(0, 0, 0, 0);
    }
    s = warpReduceSum(s);
    sq = warpReduceSum(sq);
    float mu = s * (1.f / (float)CH);
    float rs = rsqrtf(sq * (1.f / (float)CH) - mu * mu + 1e-5f);
    float yn = 0.f;
    #pragma unroll
    for (int i = 0; i < 6; i++) {
        int idx = i * 32 + lane;
        if (idx < 180) {
            float4 g4 = ((const float4*)gamma)[idx];
            float4 b4 = ((const float4*)beta)[idx];
            float a = (v[i].x - mu) * rs * g4.x + b4.x;
            float b = (v[i].y - mu) * rs * g4.y + b4.y;
            float c = (v[i].z - mu) * rs * g4.z + b4.z;
            float d = (v[i].w - mu) * rs * g4.w + b4.w;
            yn += a * a + b * b + c * c + d * d;
        }
    }
    yn = warpReduceSum(yn);
    float inv = 1.f / fmaxf(sqrtf(yn), 1e-12f);
    if (lane == 0) { g_mu[n] = mu; g_P[n] = rs * inv; g_Q[n] = inv; }
}

// ---------------- K1: normalize prototypes (fp16 + fp32) + init ----------------
__global__ __launch_bounds__(192) void kprotoB(const float* __restrict__ proto) {
    int p = blockIdx.x;
    int t = threadIdx.x;
    __shared__ float sh[32];
    if (p == JN) {
        ((uint2*)(g_Bh + (size_t)190 * CHP))[t] = make_uint2(0u, 0u);
        ((uint2*)(g_Bh + (size_t)191 * CHP))[t] = make_uint2(0u, 0u);
        if (t < KC) { g_S[t] = 0.f; g_cnt[t] = 0; }
        if (t == 0) { g_bar = 0u; g_fixcnt = 0; }
        for (int j = t; j < 3 * JN; j += 192) ((float*)g_T3)[j] = 0.f;
        return;
    }
    int k = p / MP, m = p % MP;
    int j = m * KC + k;
    const float4* pr = (const float4*)(proto + (size_t)p * CH);
    float4 v = make_float4(0, 0, 0, 0);
    float ss = 0.f;
    if (t < 180) {
        v = pr[t];
        ss = v.x * v.x + v.y * v.y + v.z * v.z + v.w * v.w;
    }
    ss = blockReduceSum(ss, sh);
    float inv = 1.f / fmaxf(sqrtf(ss), 1e-12f);
    uint2 h = make_uint2(0u, 0u);
    if (t < 180) {
        float4 f = make_float4(v.x * inv, v.y * inv, v.z * inv, v.w * inv);
        __half2 h0 = __floats2half2_rn(f.x, f.y);
        __half2 h1 = __floats2half2_rn(f.z, f.w);
        h.x = *(unsigned*)&h0;
        h.y = *(unsigned*)&h1;
        ((float4*)(g_Bf + (size_t)j * CH))[t] = f;
    }
    ((uint2*)(g_Bh + (size_t)j * CHP))[t] = h;
}

// ---------------- K2: HMMA fp16 GEMM 128x192 (round-11 exact, 143.3us) ----------------
#define STG 57344
#define GEMM_SMEM (2 * STG)

__global__ __launch_bounds__(256, 1) void kgemm_mma(const float* __restrict__ x,
                                                    const float* __restrict__ gamma,
                                                    const float* __restrict__ beta,
                                                    float* __restrict__ sim, int N) {
    extern __shared__ char smem[];
    const uint32_t sb = smem_u32(smem);

    int tid = threadIdx.x;
    int lane = tid & 31, warp = tid >> 5;        // 8 warps
    int wm = warp & 3, wn = warp >> 2;           // 4 M x 2 N
    int rowBase = (int)blockIdx.x * 128;

    int arow = tid >> 4, aq = tid & 15;          // A: rows arow + r*16 (r<8)
    int brow = tid >> 3, bq = tid & 7;           // B: rows brow + r*32 (r<6)

    float mu[8], Pv[8], Qv[8];
    #pragma unroll
    for (int r = 0; r < 8; r++) {
        int gr = rowBase + arow + r * 16;
        if (gr < N) { mu[r] = g_mu[gr]; Pv[r] = g_P[gr]; Qv[r] = g_Q[gr]; }
        else        { mu[r] = 0.f; Pv[r] = 0.f; Qv[r] = 0.f; }
    }

    float acc[2][12][4];
    #pragma unroll
    for (int t = 0; t < 2; t++)
        #pragma unroll
        for (int nt = 0; nt < 12; nt++)
            #pragma unroll
            for (int i = 0; i < 4; i++) acc[t][nt][i] = 0.f;

    float4 xr[8], g4, b4;

    auto convertA = [&](uint32_t st) {
        #pragma unroll
        for (int r = 0; r < 8; r++) {
            float yx = (xr[r].x - mu[r]) * Pv[r] * g4.x + Qv[r] * b4.x;
            float yy = (xr[r].y - mu[r]) * Pv[r] * g4.y + Qv[r] * b4.y;
            float yz = (xr[r].z - mu[r]) * Pv[r] * g4.z + Qv[r] * b4.z;
            float yw = (xr[r].w - mu[r]) * Pv[r] * g4.w + Qv[r] * b4.w;
            unsigned h0, l0, h1, l1;
            split2h(yx, yy, h0, l0);
            split2h(yz, yw, h1, l1);
            int row = arow + r * 16;
            uint32_t off = (uint32_t)(row * 128 + ((aq * 8) ^ ((row & 7) << 4)));
            asm volatile("st.shared.v2.b32 [%0], {%1,%2};" :: "r"(st + off), "r"(h0), "r"(h1));
            asm volatile("st.shared.v2.b32 [%0], {%1,%2};" :: "r"(st + 16384 + off), "r"(l0), "r"(l1));
        }
    };

    auto mma_step = [&](int s, uint32_t sAhi, uint32_t sAlo, uint32_t sB) {
        uint32_t ahi[2][4], alo[2][4], bh[6][4];
        uint32_t kb = (uint32_t)(s * 32 + ((lane >> 4) & 1) * 16);
        #pragma unroll
        for (int t = 0; t < 2; t++) {
            int row = wm * 32 + t * 16 + (lane & 15);
            uint32_t off = (uint32_t)(row * 128) + (kb ^ ((uint32_t)(row & 7) << 4));
            LDMX4(ahi[t][0], ahi[t][1], ahi[t][2], ahi[t][3], sAhi + off);
            LDMX4(alo[t][0], alo[t][1], alo[t][2], alo[t][3], sAlo + off);
        }
        #pragma unroll
        for (int g = 0; g < 6; g++) {
            int row = wn * 96 + g * 16 + (lane & 15);
            uint32_t off = (uint32_t)(row * 128) + (kb ^ ((uint32_t)(row & 7) << 4));
            LDMX4(bh[g][0], bh[g][1], bh[g][2], bh[g][3], sB + off);
        }
        #pragma unroll
        for (int t = 0; t < 2; t++)
            #pragma unroll
            for (int g = 0; g < 6; g++)
                #pragma unroll
                for (int h = 0; h < 2; h++) {
                    int nt = g * 2 + h;
                    MMA16816H(acc[t][nt], ahi[t], bh[g][h], bh[g][h + 2]);
                    MMA16816H(acc[t][nt], alo[t], bh[g][h], bh[g][h + 2]);
                }
    };

    // ======== prologue ========
    {
        uint32_t sB = sb + 32768;
        #pragma unroll
        for (int r = 0; r < 6; r++) {
            int row = brow + r * 32;
            uint32_t off = (uint32_t)(row * 128 + ((bq * 16) ^ ((row & 7) << 4)));
            CP_ASYNC16(sB + off, (const char*)(g_Bh + (size_t)row * CHP) + bq * 16);
        }
        asm volatile("cp.async.commit_group;" ::: "memory");

        g4 = ((const float4*)gamma)[aq];
        b4 = ((const float4*)beta)[aq];
        #pragma unroll
        for (int r = 0; r < 8; r++) {
            int gr = rowBase + arow + r * 16;
            xr[r] = (gr < N) ? ((const float4*)(x + (size_t)gr * CH))[aq]
                             : make_float4(0, 0, 0, 0);
        }
        convertA(sb);

        uint32_t nB = sb + STG + 32768;
        #pragma unroll
        for (int r = 0; r < 6; r++) {
            int row = brow + r * 32;
            uint32_t off = (uint32_t)(row * 128 + ((bq * 16) ^ ((row & 7) << 4)));
            CP_ASYNC16(nB + off, (const char*)(g_Bh + (size_t)row * CHP + 64) + bq * 16);
        }
        asm volatile("cp.async.commit_group;" ::: "memory");

        g4 = ((const float4*)gamma)[16 + aq];
        b4 = ((const float4*)beta)[16 + aq];
        #pragma unroll
        for (int r = 0; r < 8; r++) {
            int gr = rowBase + arow + r * 16;
            xr[r] = (gr < N) ? ((const float4*)(x + (size_t)gr * CH))[16 + aq]
                             : make_float4(0, 0, 0, 0);
        }

        asm volatile("cp.async.wait_group 1;" ::: "memory");
        __syncthreads();
    }

    // ======== main loop ========
    for (int c = 0; c < 12; c++) {
        uint32_t st = sb + (uint32_t)(c & 1) * STG;
        uint32_t sAhi = st, sAlo = st + 16384, sB = st + 32768;

        mma_step(0, sAhi, sAlo, sB);

        if (c < 11) {
            convertA(sb + (uint32_t)((c + 1) & 1) * STG);
            if (c < 10) {
                int c0 = (c + 2) * 64;
                bool kin = (c0 + aq * 4) < CH;
                g4 = kin ? ((const float4*)gamma)[(c0 >> 2) + aq] : make_float4(0, 0, 0, 0);
                b4 = kin ? ((const float4*)beta)[(c0 >> 2) + aq]  : make_float4(0, 0, 0, 0);
                #pragma unroll
                for (int r = 0; r < 8; r++) {
                    int gr = rowBase + arow + r * 16;
                    xr[r] = (kin && gr < N) ? ((const float4*)(x + (size_t)gr * CH))[(c0 >> 2) + aq]
                                            : make_float4(0, 0, 0, 0);
                }
            }
        }

        if (c != 11) {
            mma_step(1, sAhi, sAlo, sB);
            mma_step(2, sAhi, sAlo, sB);
            mma_step(3, sAhi, sAlo, sB);
        }

        if (c < 11) asm volatile("cp.async.wait_group 0;" ::: "memory");
        __syncthreads();

        if (c < 10) {
            int c0 = (c + 2) * 64;
            uint32_t nB = sb + (uint32_t)(c & 1) * STG + 32768;
            #pragma unroll
            for (int r = 0; r < 6; r++) {
                int row = brow + r * 32;
                uint32_t off = (uint32_t)(row * 128 + ((bq * 16) ^ ((row & 7) << 4)));
                CP_ASYNC16(nB + off, (const char*)(g_Bh + (size_t)row * CHP + c0) + bq * 16);
            }
            asm volatile("cp.async.commit_group;" ::: "memory");
        }
    }

    // ======== epilogue ========
    #pragma unroll
    for (int t = 0; t < 2; t++) {
        int r0 = rowBase + wm * 32 + t * 16 + (lane >> 2);
        #pragma unroll
        for (int nt = 0; nt < 12; nt++) {
            int cc = wn * 96 + nt * 8 + ((lane & 3) << 1);
            if (cc < JN) {
                if (r0 < N)
                    *(float2*)(sim + (size_t)r0 * JN + cc) =
                        make_float2(acc[t][nt][0], acc[t][nt][1]);
                if (r0 + 8 < N)
                    *(float2*)(sim + (size_t)(r0 + 8) * JN + cc) =
                        make_float2(acc[t][nt][2], acc[t][nt][3]);
            }
        }
    }
}

// ---------------- K3: kpix (lean round-11 version: 42 regs, ~19us) ----------------
#define KPIX_SMEM (64 * JN * 4)
__global__ __launch_bounds__(128) void kpix(const float* __restrict__ sim,
                                            const int* __restrict__ gt,
                                            float* __restrict__ pred_out, int N) {
    extern __shared__ float srow[];
    __shared__ float sS[KC];
    __shared__ int sC[KC];
    if (threadIdx.x < KC) { sS[threadIdx.x] = 0.f; sC[threadIdx.x] = 0; }
    int base = blockIdx.x * 64;
    int npix = min(64, N - base);
    if (npix <= 0) return;
    int n4 = npix * JN / 2;
    const float2* src = (const float2*)(sim + (size_t)base * JN);
    float2* dst = (float2*)srow;
    for (int i = threadIdx.x; i < n4; i += 128) dst[i] = src[i];
    __syncthreads();
    if (threadIdx.x < npix) {
        int n = base + threadIdx.x;
        const float* row = srow + threadIdx.x * JN;
        int g = gt[n];
        float mk[KC];
        float best = -3.4e38f; int bk = 0;
        #pragma unroll
        for (int k = 0; k < KC; k++) {
            float m0 = row[k];
            #pragma unroll
            for (int m = 1; m < MP; m++) m0 = fmaxf(m0, row[m * KC + k]);
            mk[k] = m0;
            if (m0 > best) { best = m0; bk = k; }
        }
        pred_out[n] = (float)bk;
        unsigned mask = 0; int ccount = 0;
        float thr = best - TAU;
        #pragma unroll
        for (int k = 0; k < KC; k++)
            if (mk[k] > thr) { mask |= (1u << k); ccount++; }
        if (ccount > 1) {
            int idx = atomicAdd(&g_fixcnt, 1);
            g_fixn[idx] = n;
            g_fixmask[idx] = mask;
        }
        float se = 0.f;
        #pragma unroll
        for (int m = 0; m < MP; m++) {
            float e = expf(row[m * KC + g] * 20.0f);
            g_e[(size_t)n * MP + m] = e;
            se += e;
        }
        atomicAdd(&sS[g], se);
        atomicAdd(&sC[g], 1);
    }
    __syncthreads();
    if (threadIdx.x < KC) {
        if (sS[threadIdx.x] != 0.f) atomicAdd(&g_S[threadIdx.x], sS[threadIdx.x]);
        if (sC[threadIdx.x] != 0)   atomicAdd(&g_cnt[threadIdx.x], sC[threadIdx.x]);
    }
}

// ---------------- K4: exact fp32 argmax fixup (separate, overlapped with ksink) ----------------
__global__ __launch_bounds__(256) void kfix(const float* __restrict__ x,
                                            const float* __restrict__ gamma,
                                            const float* __restrict__ beta,
                                            float* __restrict__ pred_out) {
    int lane = threadIdx.x & 31;
    int warp = (blockIdx.x * blockDim.x + threadIdx.x) >> 5;
    int nwarp = (gridDim.x * blockDim.x) >> 5;
    int cnt = g_fixcnt;
    for (int i = warp; i < cnt; i += nwarp) {
        int n = g_fixn[i];
        unsigned mask = g_fixmask[i];
        float mu = g_mu[n], P = g_P[n], Q = g_Q[n];
        const float4* xr = (const float4*)(x + (size_t)n * CH);
        float4 xn[6];
        #pragma unroll
        for (int q = 0; q < 6; q++) {
            int idx = q * 32 + lane;
            if (idx < 180) {
                float4 v = xr[idx];
                float4 g4 = ((const float4*)gamma)[idx];
                float4 b4 = ((const float4*)beta)[idx];
                xn[q].x = (v.x - mu) * P * g4.x + Q * b4.x;
                xn[q].y = (v.y - mu) * P * g4.y + Q * b4.y;
                xn[q].z = (v.z - mu) * P * g4.z + Q * b4.z;
                xn[q].w = (v.w - mu) * P * g4.w + Q * b4.w;
            } else xn[q] = make_float4(0, 0, 0, 0);
        }
        float best = -3.4e38f; int bk = 0;
        for (int k = 0; k < KC; k++) {
            if (!((mask >> k) & 1u)) continue;
            float smax = -3.4e38f;
            for (int m = 0; m < MP; m++) {
                const float4* pr = (const float4*)(g_Bf + (size_t)(m * KC + k) * CH);
                float d = 0.f;
                #pragma unroll
                for (int q = 0; q < 6; q++) {
                    int idx = q * 32 + lane;
                    if (idx < 180) {
                        float4 p = pr[idx];
                        d += xn[q].x * p.x + xn[q].y * p.y + xn[q].z * p.z + xn[q].w * p.w;
                    }
                }
                d = warpReduceSum(d);
                smax = fmaxf(smax, d);
            }
            if (smax > best) { best = smax; bk = k; }  // ascending k, strict > = first-occurrence
        }
        if (lane == 0) pred_out[n] = (float)bk;
    }
}

// ---------------- K5: fused sinkhorn (grid-barriered) ----------------
__device__ __forceinline__ void gridbar(unsigned target) {
    __threadfence();
    __syncthreads();
    if (threadIdx.x == 0) {
        atomicAdd(&g_bar, 1u);
        while (*((volatile unsigned*)&g_bar) < target) {}
    }
    __syncthreads();
}

__global__ __launch_bounds__(256) void ksink(const int* __restrict__ gt,
                                             float* __restrict__ qout, int N) {
    __shared__ float sr[JN];
    __shared__ float sT[JN];
    int tid = threadIdx.x;
    int n = blockIdx.x * 256 + tid;
    bool act = (n < N);
    int g = act ? gt[n] : 0;
    float e[MP];
    float ns = 1.f, c = 0.f;
    if (act) {
        #pragma unroll
        for (int m = 0; m < MP; m++) e[m] = g_e[(size_t)n * MP + m];
        ns = fmaxf((float)g_cnt[g], 1.f);
        c = 1.f / fmaxf(g_S[g], 1e-12f);          // c0
    }

    // phase 0: T1
    for (int j = tid; j < JN; j += 256) sT[j] = 0.f;
    __syncthreads();
    if (act) {
        #pragma unroll
        for (int m = 0; m < MP; m++) atomicAdd(&sT[g * MP + m], c * e[m]);
    }
    __syncthreads();
    for (int j = tid; j < JN; j += 256)
        if (sT[j] != 0.f) atomicAdd(&g_T3[0][j], sT[j]);
    gridbar(gridDim.x);

    // phase 1: r1, c1, T2
    if (tid < JN) {
        float r = 1.f / (fmaxf(__ldcg(&g_T3[0][tid]), 1e-12f) * (float)MP);
        sr[tid] = r;
    }
    __syncthreads();
    for (int j = tid; j < JN; j += 256) sT[j] = 0.f;
    __syncthreads();
    if (act) {
        float V = 0.f;
        #pragma unroll
        for (int m = 0; m < MP; m++) V += e[m] * sr[g * MP + m];
        c = c / (fmaxf(c * V, 1e-12f) * ns);
        #pragma unroll
        for (int m = 0; m < MP; m++) atomicAdd(&sT[g * MP + m], c * e[m]);
    }
    __syncthreads();
    for (int j = tid; j < JN; j += 256)
        if (sT[j] != 0.f) atomicAdd(&g_T3[1][j], sT[j]);
    gridbar(2u * gridDim.x);

    // phase 2: r2, c2, T3
    if (tid < JN) {
        float r = 1.f / (fmaxf(__ldcg(&g_T3[0][tid]), 1e-12f) * (float)MP);
        r = r / (fmaxf(r * __ldcg(&g_T3[1][tid]), 1e-12f) * (float)MP);
        sr[tid] = r;
    }
    __syncthreads();
    for (int j = tid; j < JN; j += 256) sT[j] = 0.f;
    __syncthreads();
    if (act) {
        float V = 0.f;
        #pragma unroll
        for (int m = 0; m < MP; m++) V += e[m] * sr[g * MP + m];
        c = c / (fmaxf(c * V, 1e-12f) * ns);
        #pragma unroll
        for (int m = 0; m < MP; m++) atomicAdd(&sT[g * MP + m], c * e[m]);
    }
    __syncthreads();
    for (int j = tid; j < JN; j += 256)
        if (sT[j] != 0.f) atomicAdd(&g_T3[2][j], sT[j]);
    gridbar(3u * gridDim.x);

    // phase 3: r3, c3, q scatter
    if (tid < JN) {
        float r = 1.f / (fmaxf(__ldcg(&g_T3[0][tid]), 1e-12f) * (float)MP);
        r = r / (fmaxf(r * __ldcg(&g_T3[1][tid]), 1e-12f) * (float)MP);
        r = r / (fmaxf(r * __ldcg(&g_T3[2][tid]), 1e-12f) * (float)MP);
        sr[tid] = r;
    }
    __syncthreads();
    if (act) {
        float V = 0.f;
        #pragma unroll
        for (int m = 0; m < MP; m++) V += e[m] * sr[g * MP + m];
        c = c / (fmaxf(c * V, 1e-12f) * ns);
        float cs = c * ns;
        size_t base = ((size_t)g * N + n) * MP;
        #pragma unroll
        for (int m = 0; m < MP; m++)
            qout[base + m] = cs * e[m] * sr[g * MP + m];
    }
}

// ---------------- launch (stream fork/join; kfix overlaps ksink) ----------------
extern "C" void kernel_launch(void* const* d_in, const int* in_sizes, int n_in,
                              void* d_out, int out_size) {
    const float* x     = (const float*)d_in[0];
    const int*   gt    = (const int*)d_in[1];
    const float* gamma = (const float*)d_in[2];
    const float* beta  = (const float*)d_in[3];
    const float* proto = (const float*)d_in[4];
    int N = in_sizes[0] / CH;

    float* out  = (float*)d_out;
    float* sim  = out;
    float* q    = out + (size_t)N * JN;
    float* pred = out + 2 * (size_t)N * JN;

    static cudaStream_t s1 = nullptr;
    static cudaEvent_t evFork = nullptr, evProto = nullptr, evMemset = nullptr,
                       evPix = nullptr, evFix = nullptr;
    if (!s1) {   // created on the first (uncaptured) correctness call
        cudaStreamCreateWithFlags(&s1, cudaStreamNonBlocking);
        cudaEventCreateWithFlags(&evFork, cudaEventDisableTiming);
        cudaEventCreateWithFlags(&evProto, cudaEventDisableTiming);
        cudaEventCreateWithFlags(&evMemset, cudaEventDisableTiming);
        cudaEventCreateWithFlags(&evPix, cudaEventDisableTiming);
        cudaEventCreateWithFlags(&evFix, cudaEventDisableTiming);
        cudaFuncSetAttribute(kgemm_mma, cudaFuncAttributeMaxDynamicSharedMemorySize, GEMM_SMEM);
        cudaFuncSetAttribute(kpix, cudaFuncAttributeMaxDynamicSharedMemorySize, KPIX_SMEM);
    }

    // fork: side stream does kprotoB then q-memset while main does kstats
    cudaEventRecord(evFork, 0);
    cudaStreamWaitEvent(s1, evFork, 0);

    kprotoB<<<JN + 1, 192, 0, s1>>>(proto);
    cudaEventRecord(evProto, s1);
    cudaMemsetAsync(q, 0, (size_t)N * JN * sizeof(float), s1);
    cudaEventRecord(evMemset, s1);

    kstats<<<(N + 7) / 8, 256>>>(x, gamma, beta, N);

    cudaStreamWaitEvent(0, evProto, 0);     // GEMM needs g_Bh (+ inits)
    kgemm_mma<<<(N + 127) / 128, 256, GEMM_SMEM>>>(x, gamma, beta, sim, N);
    kpix<<<(N + 63) / 64, 128, KPIX_SMEM>>>(sim, gt, pred, N);
    cudaEventRecord(evPix, 0);

    // kfix on side stream, overlapped with ksink (independent outputs)
    cudaStreamWaitEvent(s1, evPix, 0);
    kfix<<<256, 256, 0, s1>>>(x, gamma, beta, pred);
    cudaEventRecord(evFix, s1);

    cudaStreamWaitEvent(0, evMemset, 0);    // q zeroed before ksink writes
    ksink<<<(N + 255) / 256, 256>>>(gt, q, N);
    cudaStreamWaitEvent(0, evFix, 0);       // join side stream before capture end
}

// round 17
// speedup vs baseline: 1.1616x; 1.0490x over previous
#include <cuda_runtime.h>
#include <cuda_fp16.h>
#include <math.h>
#include <stdint.h>

#define KC 19
#define MP 10
#define CH 720
#define CHP 768
#define JN 190
#define JP 192
#define NMAX 65536
#define TAU 6e-4f

// ---------------- scratch ----------------
__device__ __align__(256) __half g_Bh[JP * CHP];
__device__ __align__(256) float g_Bf[(size_t)JN * CH];
__device__ float g_mu[NMAX];
__device__ float g_P[NMAX];
__device__ float g_Q[NMAX];
__device__ float g_e[(size_t)NMAX * MP];
__device__ float g_S[KC];
__device__ int   g_cnt[KC];
__device__ float g_T3[3][JN];
__device__ unsigned g_bar;
__device__ int      g_fixcnt;
__device__ int      g_fixn[NMAX];
__device__ unsigned g_fixmask[NMAX];

// ---------------- helpers ----------------
__device__ __forceinline__ uint32_t smem_u32(const void* p) {
    uint32_t a;
    asm("{ .reg .u64 t; cvta.to.shared.u64 t, %1; cvt.u32.u64 %0, t; }" : "=r"(a) : "l"(p));
    return a;
}
__device__ __forceinline__ float warpReduceSum(float v) {
    #pragma unroll
    for (int o = 16; o > 0; o >>= 1) v += __shfl_xor_sync(0xffffffffu, v, o);
    return v;
}
__device__ __forceinline__ float blockReduceSum(float v, float* sh) {
    __syncthreads();
    v = warpReduceSum(v);
    int lane = threadIdx.x & 31, w = threadIdx.x >> 5;
    if (lane == 0) sh[w] = v;
    __syncthreads();
    int nw = (blockDim.x + 31) >> 5;
    v = (threadIdx.x < nw) ? sh[threadIdx.x] : 0.f;
    if (w == 0) { v = warpReduceSum(v); if (lane == 0) sh[0] = v; }
    __syncthreads();
    return sh[0];
}
__device__ __forceinline__ void split2h(float a0, float a1, unsigned& h, unsigned& l) {
    __half2 hh = __floats2half2_rn(a0, a1);
    float2 hf = __half22float2(hh);
    __half2 ll = __floats2half2_rn(a0 - hf.x, a1 - hf.y);
    h = *(unsigned*)&hh;
    l = *(unsigned*)&ll;
}

#define LDMX4(r0, r1, r2, r3, addr) \
    asm volatile("ldmatrix.sync.aligned.m8n8.x4.shared.b16 {%0,%1,%2,%3}, [%4];" \
                 : "=r"(r0), "=r"(r1), "=r"(r2), "=r"(r3) : "r"(addr))

#define MMA16816H(d, a, b0, b1) \
    asm volatile("mma.sync.aligned.m16n8k16.row.col.f32.f16.f16.f32 " \
                 "{%0,%1,%2,%3}, {%4,%5,%6,%7}, {%8,%9}, {%0,%1,%2,%3};" \
                 : "+f"((d)[0]), "+f"((d)[1]), "+f"((d)[2]), "+f"((d)[3]) \
                 : "r"((a)[0]), "r"((a)[1]), "r"((a)[2]), "r"((a)[3]), "r"(b0), "r"(b1))

#define CP_ASYNC16(dst, src) \
    asm volatile("cp.async.ca.shared.global [%0], [%1], 16;" \
                 :: "r"(dst), "l"(src) : "memory")

// ---------------- K0: warp-per-row stats (rows [off, off+cnt)) ----------------
__global__ __launch_bounds__(256) void kstats(const float* __restrict__ x,
                                              const float* __restrict__ gamma,
                                              const float* __restrict__ beta,
                                              int off, int cnt, int N) {
    int warp = threadIdx.x >> 5, lane = threadIdx.x & 31;
    int n = off + blockIdx.x * 8 + warp;
    if (n >= off + cnt || n >= N) return;
    const float4* xr = (const float4*)(x + (size_t)n * CH);
    float4 v[6];
    float s = 0.f, sq = 0.f;
    #pragma unroll
    for (int i = 0; i < 6; i++) {
        int idx = i * 32 + lane;
        if (idx < 180) {
            v[i] = xr[idx];
            s += v[i].x + v[i].y + v[i].z + v[i].w;
            sq += v[i].x * v[i].x + v[i].y * v[i].y + v[i].z * v[i].z + v[i].w * v[i].w;
        } else v[i] = make_float4(0, 0, 0, 0);
    }
    s = warpReduceSum(s);
    sq = warpReduceSum(sq);
    float mu = s * (1.f / (float)CH);
    float rs = rsqrtf(sq * (1.f / (float)CH) - mu * mu + 1e-5f);
    float yn = 0.f;
    #pragma unroll
    for (int i = 0; i < 6; i++) {
        int idx = i * 32 + lane;
        if (idx < 180) {
            float4 g4 = ((const float4*)gamma)[idx];
            float4 b4 = ((const float4*)beta)[idx];
            float a = (v[i].x - mu) * rs * g4.x + b4.x;
            float b = (v[i].y - mu) * rs * g4.y + b4.y;
            float c = (v[i].z - mu) * rs * g4.z + b4.z;
            float d = (v[i].w - mu) * rs * g4.w + b4.w;
            yn += a * a + b * b + c * c + d * d;
        }
    }
    yn = warpReduceSum(yn);
    float inv = 1.f / fmaxf(sqrtf(yn), 1e-12f);
    if (lane == 0) { g_mu[n] = mu; g_P[n] = rs * inv; g_Q[n] = inv; }
}

// ---------------- K1: normalize prototypes + init ----------------
__global__ __launch_bounds__(192) void kprotoB(const float* __restrict__ proto) {
    int p = blockIdx.x;
    int t = threadIdx.x;
    __shared__ float sh[32];
    if (p == JN) {
        ((uint2*)(g_Bh + (size_t)190 * CHP))[t] = make_uint2(0u, 0u);
        ((uint2*)(g_Bh + (size_t)191 * CHP))[t] = make_uint2(0u, 0u);
        if (t < KC) { g_S[t] = 0.f; g_cnt[t] = 0; }
        if (t == 0) { g_bar = 0u; g_fixcnt = 0; }
        for (int j = t; j < 3 * JN; j += 192) ((float*)g_T3)[j] = 0.f;
        return;
    }
    int k = p / MP, m = p % MP;
    int j = m * KC + k;
    const float4* pr = (const float4*)(proto + (size_t)p * CH);
    float4 v = make_float4(0, 0, 0, 0);
    float ss = 0.f;
    if (t < 180) {
        v = pr[t];
        ss = v.x * v.x + v.y * v.y + v.z * v.z + v.w * v.w;
    }
    ss = blockReduceSum(ss, sh);
    float inv = 1.f / fmaxf(sqrtf(ss), 1e-12f);
    uint2 h = make_uint2(0u, 0u);
    if (t < 180) {
        float4 f = make_float4(v.x * inv, v.y * inv, v.z * inv, v.w * inv);
        __half2 h0 = __floats2half2_rn(f.x, f.y);
        __half2 h1 = __floats2half2_rn(f.z, f.w);
        h.x = *(unsigned*)&h0;
        h.y = *(unsigned*)&h1;
        ((float4*)(g_Bf + (size_t)j * CH))[t] = f;
    }
    ((uint2*)(g_Bh + (size_t)j * CHP))[t] = h;
}

// ---------------- K2: HMMA fp16 GEMM 128x192 (round-11 core + row offset) ----------------
#define STG 57344
#define GEMM_SMEM (2 * STG)

__global__ __launch_bounds__(256, 1) void kgemm_mma(const float* __restrict__ x,
                                                    const float* __restrict__ gamma,
                                                    const float* __restrict__ beta,
                                                    float* __restrict__ sim,
                                                    int off, int N) {
    extern __shared__ char smem[];
    const uint32_t sb = smem_u32(smem);

    int tid = threadIdx.x;
    int lane = tid & 31, warp = tid >> 5;
    int wm = warp & 3, wn = warp >> 2;
    int rowBase = off + (int)blockIdx.x * 128;

    int arow = tid >> 4, aq = tid & 15;
    int brow = tid >> 3, bq = tid & 7;

    float mu[8], Pv[8], Qv[8];
    #pragma unroll
    for (int r = 0; r < 8; r++) {
        int gr = rowBase + arow + r * 16;
        if (gr < N) { mu[r] = g_mu[gr]; Pv[r] = g_P[gr]; Qv[r] = g_Q[gr]; }
        else        { mu[r] = 0.f; Pv[r] = 0.f; Qv[r] = 0.f; }
    }

    float acc[2][12][4];
    #pragma unroll
    for (int t = 0; t < 2; t++)
        #pragma unroll
        for (int nt = 0; nt < 12; nt++)
            #pragma unroll
            for (int i = 0; i < 4; i++) acc[t][nt][i] = 0.f;

    float4 xr[8], g4, b4;

    auto convertA = [&](uint32_t st) {
        #pragma unroll
        for (int r = 0; r < 8; r++) {
            float yx = (xr[r].x - mu[r]) * Pv[r] * g4.x + Qv[r] * b4.x;
            float yy = (xr[r].y - mu[r]) * Pv[r] * g4.y + Qv[r] * b4.y;
            float yz = (xr[r].z - mu[r]) * Pv[r] * g4.z + Qv[r] * b4.z;
            float yw = (xr[r].w - mu[r]) * Pv[r] * g4.w + Qv[r] * b4.w;
            unsigned h0, l0, h1, l1;
            split2h(yx, yy, h0, l0);
            split2h(yz, yw, h1, l1);
            int row = arow + r * 16;
            uint32_t offb = (uint32_t)(row * 128 + ((aq * 8) ^ ((row & 7) << 4)));
            asm volatile("st.shared.v2.b32 [%0], {%1,%2};" :: "r"(st + offb), "r"(h0), "r"(h1));
            asm volatile("st.shared.v2.b32 [%0], {%1,%2};" :: "r"(st + 16384 + offb), "r"(l0), "r"(l1));
        }
    };

    auto mma_step = [&](int s, uint32_t sAhi, uint32_t sAlo, uint32_t sB) {
        uint32_t ahi[2][4], alo[2][4], bh[6][4];
        uint32_t kb = (uint32_t)(s * 32 + ((lane >> 4) & 1) * 16);
        #pragma unroll
        for (int t = 0; t < 2; t++) {
            int row = wm * 32 + t * 16 + (lane & 15);
            uint32_t offb = (uint32_t)(row * 128) + (kb ^ ((uint32_t)(row & 7) << 4));
            LDMX4(ahi[t][0], ahi[t][1], ahi[t][2], ahi[t][3], sAhi + offb);
            LDMX4(alo[t][0], alo[t][1], alo[t][2], alo[t][3], sAlo + offb);
        }
        #pragma unroll
        for (int g = 0; g < 6; g++) {
            int row = wn * 96 + g * 16 + (lane & 15);
            uint32_t offb = (uint32_t)(row * 128) + (kb ^ ((uint32_t)(row & 7) << 4));
            LDMX4(bh[g][0], bh[g][1], bh[g][2], bh[g][3], sB + offb);
        }
        #pragma unroll
        for (int t = 0; t < 2; t++)
            #pragma unroll
            for (int g = 0; g < 6; g++)
                #pragma unroll
                for (int h = 0; h < 2; h++) {
                    int nt = g * 2 + h;
                    MMA16816H(acc[t][nt], ahi[t], bh[g][h], bh[g][h + 2]);
                    MMA16816H(acc[t][nt], alo[t], bh[g][h], bh[g][h + 2]);
                }
    };

    // prologue
    {
        uint32_t sB = sb + 32768;
        #pragma unroll
        for (int r = 0; r < 6; r++) {
            int row = brow + r * 32;
            uint32_t offb = (uint32_t)(row * 128 + ((bq * 16) ^ ((row & 7) << 4)));
            CP_ASYNC16(sB + offb, (const char*)(g_Bh + (size_t)row * CHP) + bq * 16);
        }
        asm volatile("cp.async.commit_group;" ::: "memory");

        g4 = ((const float4*)gamma)[aq];
        b4 = ((const float4*)beta)[aq];
        #pragma unroll
        for (int r = 0; r < 8; r++) {
            int gr = rowBase + arow + r * 16;
            xr[r] = (gr < N) ? ((const float4*)(x + (size_t)gr * CH))[aq]
                             : make_float4(0, 0, 0, 0);
        }
        convertA(sb);

        uint32_t nB = sb + STG + 32768;
        #pragma unroll
        for (int r = 0; r < 6; r++) {
            int row = brow + r * 32;
            uint32_t offb = (uint32_t)(row * 128 + ((bq * 16) ^ ((row & 7) << 4)));
            CP_ASYNC16(nB + offb, (const char*)(g_Bh + (size_t)row * CHP + 64) + bq * 16);
        }
        asm volatile("cp.async.commit_group;" ::: "memory");

        g4 = ((const float4*)gamma)[16 + aq];
        b4 = ((const float4*)beta)[16 + aq];
        #pragma unroll
        for (int r = 0; r < 8; r++) {
            int gr = rowBase + arow + r * 16;
            xr[r] = (gr < N) ? ((const float4*)(x + (size_t)gr * CH))[16 + aq]
                             : make_float4(0, 0, 0, 0);
        }

        asm volatile("cp.async.wait_group 1;" ::: "memory");
        __syncthreads();
    }

    // main loop
    for (int c = 0; c < 12; c++) {
        uint32_t st = sb + (uint32_t)(c & 1) * STG;
        uint32_t sAhi = st, sAlo = st + 16384, sB = st + 32768;

        mma_step(0, sAhi, sAlo, sB);

        if (c < 11) {
            convertA(sb + (uint32_t)((c + 1) & 1) * STG);
            if (c < 10) {
                int c0 = (c + 2) * 64;
                bool kin = (c0 + aq * 4) < CH;
                g4 = kin ? ((const float4*)gamma)[(c0 >> 2) + aq] : make_float4(0, 0, 0, 0);
                b4 = kin ? ((const float4*)beta)[(c0 >> 2) + aq]  : make_float4(0, 0, 0, 0);
                #pragma unroll
                for (int r = 0; r < 8; r++) {
                    int gr = rowBase + arow + r * 16;
                    xr[r] = (kin && gr < N) ? ((const float4*)(x + (size_t)gr * CH))[(c0 >> 2) + aq]
                                            : make_float4(0, 0, 0, 0);
                }
            }
        }

        if (c != 11) {
            mma_step(1, sAhi, sAlo, sB);
            mma_step(2, sAhi, sAlo, sB);
            mma_step(3, sAhi, sAlo, sB);
        }

        if (c < 11) asm volatile("cp.async.wait_group 0;" ::: "memory");
        __syncthreads();

        if (c < 10) {
            int c0 = (c + 2) * 64;
            uint32_t nB = sb + (uint32_t)(c & 1) * STG + 32768;
            #pragma unroll
            for (int r = 0; r < 6; r++) {
                int row = brow + r * 32;
                uint32_t offb = (uint32_t)(row * 128 + ((bq * 16) ^ ((row & 7) << 4)));
                CP_ASYNC16(nB + offb, (const char*)(g_Bh + (size_t)row * CHP + c0) + bq * 16);
            }
            asm volatile("cp.async.commit_group;" ::: "memory");
        }
    }

    // epilogue
    #pragma unroll
    for (int t = 0; t < 2; t++) {
        int r0 = rowBase + wm * 32 + t * 16 + (lane >> 2);
        #pragma unroll
        for (int nt = 0; nt < 12; nt++) {
            int cc = wn * 96 + nt * 8 + ((lane & 3) << 1);
            if (cc < JN) {
                if (r0 < N)
                    *(float2*)(sim + (size_t)r0 * JN + cc) =
                        make_float2(acc[t][nt][0], acc[t][nt][1]);
                if (r0 + 8 < N)
                    *(float2*)(sim + (size_t)(r0 + 8) * JN + cc) =
                        make_float2(acc[t][nt][2], acc[t][nt][3]);
            }
        }
    }
}

// ---------------- K3: kpix (lean; rows [off, off+cnt)) ----------------
#define KPIX_SMEM (64 * JN * 4)
__global__ __launch_bounds__(128) void kpix(const float* __restrict__ sim,
                                            const int* __restrict__ gt,
                                            float* __restrict__ pred_out,
                                            int off, int cnt, int N) {
    extern __shared__ float srow[];
    __shared__ float sS[KC];
    __shared__ int sC[KC];
    if (threadIdx.x < KC) { sS[threadIdx.x] = 0.f; sC[threadIdx.x] = 0; }
    int base = off + blockIdx.x * 64;
    int lim = min(off + cnt, N);
    int npix = min(64, lim - base);
    if (npix <= 0) return;
    int n4 = npix * JN / 2;
    const float2* src = (const float2*)(sim + (size_t)base * JN);
    float2* dst = (float2*)srow;
    for (int i = threadIdx.x; i < n4; i += 128) dst[i] = src[i];
    __syncthreads();
    if (threadIdx.x < npix) {
        int n = base + threadIdx.x;
        const float* row = srow + threadIdx.x * JN;
        int g = gt[n];
        float mk[KC];
        float best = -3.4e38f; int bk = 0;
        #pragma unroll
        for (int k = 0; k < KC; k++) {
            float m0 = row[k];
            #pragma unroll
            for (int m = 1; m < MP; m++) m0 = fmaxf(m0, row[m * KC + k]);
            mk[k] = m0;
            if (m0 > best) { best = m0; bk = k; }
        }
        pred_out[n] = (float)bk;
        unsigned mask = 0; int ccount = 0;
        float thr = best - TAU;
        #pragma unroll
        for (int k = 0; k < KC; k++)
            if (mk[k] > thr) { mask |= (1u << k); ccount++; }
        if (ccount > 1) {
            int idx = atomicAdd(&g_fixcnt, 1);
            g_fixn[idx] = n;
            g_fixmask[idx] = mask;
        }
        float se = 0.f;
        #pragma unroll
        for (int m = 0; m < MP; m++) {
            float e = expf(row[m * KC + g] * 20.0f);
            g_e[(size_t)n * MP + m] = e;
            se += e;
        }
        atomicAdd(&sS[g], se);
        atomicAdd(&sC[g], 1);
    }
    __syncthreads();
    if (threadIdx.x < KC) {
        if (sS[threadIdx.x] != 0.f) atomicAdd(&g_S[threadIdx.x], sS[threadIdx.x]);
        if (sC[threadIdx.x] != 0)   atomicAdd(&g_cnt[threadIdx.x], sC[threadIdx.x]);
    }
}

// ---------------- K4: exact fp32 argmax fixup ----------------
__global__ __launch_bounds__(256) void kfix(const float* __restrict__ x,
                                            const float* __restrict__ gamma,
                                            const float* __restrict__ beta,
                                            float* __restrict__ pred_out) {
    int lane = threadIdx.x & 31;
    int warp = (blockIdx.x * blockDim.x + threadIdx.x) >> 5;
    int nwarp = (gridDim.x * blockDim.x) >> 5;
    int cnt = g_fixcnt;
    for (int i = warp; i < cnt; i += nwarp) {
        int n = g_fixn[i];
        unsigned mask = g_fixmask[i];
        float mu = g_mu[n], P = g_P[n], Q = g_Q[n];
        const float4* xr = (const float4*)(x + (size_t)n * CH);
        float4 xn[6];
        #pragma unroll
        for (int q = 0; q < 6; q++) {
            int idx = q * 32 + lane;
            if (idx < 180) {
                float4 v = xr[idx];
                float4 g4 = ((const float4*)gamma)[idx];
                float4 b4 = ((const float4*)beta)[idx];
                xn[q].x = (v.x - mu) * P * g4.x + Q * b4.x;
                xn[q].y = (v.y - mu) * P * g4.y + Q * b4.y;
                xn[q].z = (v.z - mu) * P * g4.z + Q * b4.z;
                xn[q].w = (v.w - mu) * P * g4.w + Q * b4.w;
            } else xn[q] = make_float4(0, 0, 0, 0);
        }
        float best = -3.4e38f; int bk = 0;
        for (int k = 0; k < KC; k++) {
            if (!((mask >> k) & 1u)) continue;
            float smax = -3.4e38f;
            for (int m = 0; m < MP; m++) {
                const float4* pr = (const float4*)(g_Bf + (size_t)(m * KC + k) * CH);
                float d = 0.f;
                #pragma unroll
                for (int q = 0; q < 6; q++) {
                    int idx = q * 32 + lane;
                    if (idx < 180) {
                        float4 p = pr[idx];
                        d += xn[q].x * p.x + xn[q].y * p.y + xn[q].z * p.z + xn[q].w * p.w;
                    }
                }
                d = warpReduceSum(d);
                smax = fmaxf(smax, d);
            }
            if (smax > best) { best = smax; bk = k; }
        }
        if (lane == 0) pred_out[n] = (float)bk;
    }
}

// ---------------- K5: fused sinkhorn (grid-barriered) ----------------
__device__ __forceinline__ void gridbar(unsigned target) {
    __threadfence();
    __syncthreads();
    if (threadIdx.x == 0) {
        atomicAdd(&g_bar, 1u);
        while (*((volatile unsigned*)&g_bar) < target) {}
    }
    __syncthreads();
}

__global__ __launch_bounds__(256) void ksink(const int* __restrict__ gt,
                                             float* __restrict__ qout, int N) {
    __shared__ float sr[JN];
    __shared__ float sT[JN];
    int tid = threadIdx.x;
    int n = blockIdx.x * 256 + tid;
    bool act = (n < N);
    int g = act ? gt[n] : 0;
    float e[MP];
    float ns = 1.f, c = 0.f;
    if (act) {
        #pragma unroll
        for (int m = 0; m < MP; m++) e[m] = g_e[(size_t)n * MP + m];
        ns = fmaxf((float)g_cnt[g], 1.f);
        c = 1.f / fmaxf(g_S[g], 1e-12f);
    }

    // phase 0: T1
    for (int j = tid; j < JN; j += 256) sT[j] = 0.f;
    __syncthreads();
    if (act) {
        #pragma unroll
        for (int m = 0; m < MP; m++) atomicAdd(&sT[g * MP + m], c * e[m]);
    }
    __syncthreads();
    for (int j = tid; j < JN; j += 256)
        if (sT[j] != 0.f) atomicAdd(&g_T3[0][j], sT[j]);
    gridbar(gridDim.x);

    // phase 1: r1, c1, T2
    if (tid < JN) {
        float r = 1.f / (fmaxf(__ldcg(&g_T3[0][tid]), 1e-12f) * (float)MP);
        sr[tid] = r;
    }
    __syncthreads();
    for (int j = tid; j < JN; j += 256) sT[j] = 0.f;
    __syncthreads();
    if (act) {
        float V = 0.f;
        #pragma unroll
        for (int m = 0; m < MP; m++) V += e[m] * sr[g * MP + m];
        c = c / (fmaxf(c * V, 1e-12f) * ns);
        #pragma unroll
        for (int m = 0; m < MP; m++) atomicAdd(&sT[g * MP + m], c * e[m]);
    }
    __syncthreads();
    for (int j = tid; j < JN; j += 256)
        if (sT[j] != 0.f) atomicAdd(&g_T3[1][j], sT[j]);
    gridbar(2u * gridDim.x);

    // phase 2: r2, c2, T3
    if (tid < JN) {
        float r = 1.f / (fmaxf(__ldcg(&g_T3[0][tid]), 1e-12f) * (float)MP);
        r = r / (fmaxf(r * __ldcg(&g_T3[1][tid]), 1e-12f) * (float)MP);
        sr[tid] = r;
    }
    __syncthreads();
    for (int j = tid; j < JN; j += 256) sT[j] = 0.f;
    __syncthreads();
    if (act) {
        float V = 0.f;
        #pragma unroll
        for (int m = 0; m < MP; m++) V += e[m] * sr[g * MP + m];
        c = c / (fmaxf(c * V, 1e-12f) * ns);
        #pragma unroll
        for (int m = 0; m < MP; m++) atomicAdd(&sT[g * MP + m], c * e[m]);
    }
    __syncthreads();
    for (int j = tid; j < JN; j += 256)
        if (sT[j] != 0.f) atomicAdd(&g_T3[2][j], sT[j]);
    gridbar(3u * gridDim.x);

    // phase 3: r3, c3, q scatter
    if (tid < JN) {
        float r = 1.f / (fmaxf(__ldcg(&g_T3[0][tid]), 1e-12f) * (float)MP);
        r = r / (fmaxf(r * __ldcg(&g_T3[1][tid]), 1e-12f) * (float)MP);
        r = r / (fmaxf(r * __ldcg(&g_T3[2][tid]), 1e-12f) * (float)MP);
        sr[tid] = r;
    }
    __syncthreads();
    if (act) {
        float V = 0.f;
        #pragma unroll
        for (int m = 0; m < MP; m++) V += e[m] * sr[g * MP + m];
        c = c / (fmaxf(c * V, 1e-12f) * ns);
        float cs = c * ns;
        size_t base = ((size_t)g * N + n) * MP;
        #pragma unroll
        for (int m = 0; m < MP; m++)
            qout[base + m] = cs * e[m] * sr[g * MP + m];
    }
}

// ---------------- launch: two-half pipeline across streams ----------------
extern "C" void kernel_launch(void* const* d_in, const int* in_sizes, int n_in,
                              void* d_out, int out_size) {
    const float* x     = (const float*)d_in[0];
    const int*   gt    = (const int*)d_in[1];
    const float* gamma = (const float*)d_in[2];
    const float* beta  = (const float*)d_in[3];
    const float* proto = (const float*)d_in[4];
    int N = in_sizes[0] / CH;

    float* out  = (float*)d_out;
    float* sim  = out;
    float* q    = out + (size_t)N * JN;
    float* pred = out + 2 * (size_t)N * JN;

    // half split, H0 multiple of 128
    int H0 = ((N / 2) + 127) & ~127;
    if (H0 > N) H0 = N;
    int H1 = N - H0;

    static cudaStream_t s1 = nullptr;
    static cudaEvent_t evFork = nullptr, evProto = nullptr, evMemset = nullptr,
                       evS1 = nullptr, evG0 = nullptr, evPix0 = nullptr,
                       evPix1 = nullptr, evFix = nullptr;
    if (!s1) {
        cudaStreamCreateWithFlags(&s1, cudaStreamNonBlocking);
        cudaEventCreateWithFlags(&evFork, cudaEventDisableTiming);
        cudaEventCreateWithFlags(&evProto, cudaEventDisableTiming);
        cudaEventCreateWithFlags(&evMemset, cudaEventDisableTiming);
        cudaEventCreateWithFlags(&evS1, cudaEventDisableTiming);
        cudaEventCreateWithFlags(&evG0, cudaEventDisableTiming);
        cudaEventCreateWithFlags(&evPix0, cudaEventDisableTiming);
        cudaEventCreateWithFlags(&evPix1, cudaEventDisableTiming);
        cudaEventCreateWithFlags(&evFix, cudaEventDisableTiming);
        cudaFuncSetAttribute(kgemm_mma, cudaFuncAttributeMaxDynamicSharedMemorySize, GEMM_SMEM);
        cudaFuncSetAttribute(kpix, cudaFuncAttributeMaxDynamicSharedMemorySize, KPIX_SMEM);
    }

    cudaEventRecord(evFork, 0);
    cudaStreamWaitEvent(s1, evFork, 0);

    // side: proto + q memset + stats(h1)
    kprotoB<<<JN + 1, 192, 0, s1>>>(proto);
    cudaEventRecord(evProto, s1);
    cudaMemsetAsync(q, 0, (size_t)N * JN * sizeof(float), s1);
    cudaEventRecord(evMemset, s1);
    if (H1 > 0) kstats<<<(H1 + 7) / 8, 256, 0, s1>>>(x, gamma, beta, H0, H1, N);
    cudaEventRecord(evS1, s1);

    // main: stats(h0), gemm(h0)
    kstats<<<(H0 + 7) / 8, 256>>>(x, gamma, beta, 0, H0, N);
    cudaStreamWaitEvent(0, evProto, 0);
    kgemm_mma<<<H0 / 128, 256, GEMM_SMEM>>>(x, gamma, beta, sim, 0, N);
    cudaEventRecord(evG0, 0);

    // side: pix(h0) overlaps gemm(h1)
    cudaStreamWaitEvent(s1, evG0, 0);
    kpix<<<(H0 + 63) / 64, 128, KPIX_SMEM, s1>>>(sim, gt, pred, 0, H0, N);
    cudaEventRecord(evPix0, s1);

    // main: gemm(h1), pix(h1)
    if (H1 > 0) {
        cudaStreamWaitEvent(0, evS1, 0);
        kgemm_mma<<<(H1 + 127) / 128, 256, GEMM_SMEM>>>(x, gamma, beta, sim, H0, N);
        kpix<<<(H1 + 63) / 64, 128, KPIX_SMEM>>>(sim, gt, pred, H0, H1, N);
    }
    cudaEventRecord(evPix1, 0);

    // side: fixup after both pix passes; overlaps ksink
    cudaStreamWaitEvent(s1, evPix1, 0);
    kfix<<<256, 256, 0, s1>>>(x, gamma, beta, pred);
    cudaEventRecord(evFix, s1);

    // main: sinkhorn
    cudaStreamWaitEvent(0, evPix0, 0);
    cudaStreamWaitEvent(0, evMemset, 0);
    ksink<<<(N + 255) / 256, 256>>>(gt, q, N);
    cudaStreamWaitEvent(0, evFix, 0);
}